// round 13
// baseline (speedup 1.0000x reference)
#include <cuda_runtime.h>
#include <cuda_fp16.h>
#include <math.h>
#include <stdint.h>

#define BB    8
#define NPG   4096
#define NN    32768
#define EE    262144
#define INC   1024
#define HID   512
#define NCLS  4
#define K1    2048
#define K2    1024
#define NACT2 (BB*K1)
#define NACT3 (BB*K2)

// ---------------- scratch (device globals; no allocations allowed) ----------
__device__ float g_t[NN * HID];
__device__ float g_h[NN * HID];
__device__ float g_dinv[NN];
__device__ float g_nmask[NN];
__device__ float g_rows[NN];
__device__ float g_sr[NN];
__device__ float g_so[NN];
__device__ float g_score[NN];
__device__ int   g_cnt[NN];
__device__ int   g_off[NN + 1];
__device__ int   g_cur[NN];
__device__ int   g_csr[EE];
__device__ __half g_w1t_hi[HID * INC];
__device__ __half g_w1t_lo[HID * INC];
__device__ __half g_w2t_hi[HID * HID];
__device__ __half g_w2t_lo[HID * HID];
__device__ __half g_w3t_hi[HID * HID];
__device__ __half g_w3t_lo[HID * HID];
__device__ int   g_iota[NN];
__device__ int   g_ridx2[NACT2 + 64];
__device__ int   g_ridx3[NACT3 + 64];
__device__ float g_pp_sum[BB * 16 * HID];
__device__ float g_pp_max[BB * 16 * HID];

__device__ __forceinline__ float lrelu(float x) { return x > 0.f ? x : 0.01f * x; }

// ---------------- fp16 m16n8k16 mma (base-target PTX, sm_80+) ---------------
__device__ __forceinline__ void mma16(float* c, uint4 a, uint2 b) {
    asm volatile(
        "mma.sync.aligned.m16n8k16.row.col.f32.f16.f16.f32 "
        "{%0,%1,%2,%3}, {%4,%5,%6,%7}, {%8,%9}, {%0,%1,%2,%3};"
        : "+f"(c[0]), "+f"(c[1]), "+f"(c[2]), "+f"(c[3])
        : "r"(a.x), "r"(a.y), "r"(a.z), "r"(a.w), "r"(b.x), "r"(b.y));
}

// ======= fp16x3 HMMA GEMM: block 128x128, BK=32, 512 thr (16 warps 4x4) =====
#define AREG_B   576
#define AMAT_B   (16 * AREG_B)
#define BREG_B   296
#define BMAT_B   (32 * BREG_B)
#define STG_B    (2*AMAT_B + 2*BMAT_B)
#define SM_BYTES (1024 + 2 * STG_B)         /* 75776 */

__global__ void __launch_bounds__(512, 1)
mma_gemm(const float* __restrict__ A, const __half* __restrict__ Bhi,
         const __half* __restrict__ Blo, const float* __restrict__ rs,
         const int* __restrict__ ridx, float* __restrict__ C, int K)
{
    extern __shared__ char smc[];
    int*   ridx_s = (int*)smc;
    float* rs_s   = (float*)(smc + 512);
    char*  stg    = smc + 1024;

    int tid = threadIdx.x;
    int lane = tid & 31, wid = tid >> 5;
    int g = lane >> 2, tg = lane & 3;
    int wm = wid & 3, wn = wid >> 2;
    int nb = blockIdx.x, mb = blockIdx.y;

    if (tid < 128) {
        int r = ridx[mb * 128 + tid];
        ridx_s[tid] = r;
        rs_s[tid] = rs[r];
    }
    __syncthreads();

    float acc[2][4][4];
#pragma unroll
    for (int a = 0; a < 2; a++)
#pragma unroll
        for (int b = 0; b < 4; b++)
#pragma unroll
            for (int q = 0; q < 4; q++) acc[a][b][q] = 0.f;

    int jm[2], jc[2];
    const float* pa[2];
    const __half *pbh[2], *pbl[2];
#pragma unroll
    for (int i = 0; i < 2; i++) {
        int j = tid + 512 * i;
        jm[i] = j >> 3; jc[i] = (j & 7) * 4;
        pa[i]  = A   + (size_t)ridx_s[jm[i]] * K + jc[i];
        pbh[i] = Bhi + (size_t)(nb * 128 + jm[i]) * K + jc[i];
        pbl[i] = Blo + (size_t)(nb * 128 + jm[i]) * K + jc[i];
    }

    float4 sa[2];
    uint2  sbh[2], sbl[2];

    auto do_ldg = [&]() {
#pragma unroll
        for (int i = 0; i < 2; i++) {
            sa[i]  = *(const float4*)pa[i];  pa[i]  += 32;
            sbh[i] = *(const uint2*)pbh[i]; pbh[i] += 32;
            sbl[i] = *(const uint2*)pbl[i]; pbl[i] += 32;
        }
    };

    auto do_sts = [&](int s) {
        char* base = stg + s * STG_B;
#pragma unroll
        for (int i = 0; i < 2; i++) {
            int m = jm[i], c4 = jc[i];
            int k16 = c4 >> 4, kk = c4 & 15;
            int tg0 = (kk >> 1) & 3;
            int slot = ((kk >= 8) ? 2 : 0) + ((m & 15) >> 3);
            int aoff = ((m >> 4) * 2 + k16) * AREG_B + ((m & 7) * 4 + tg0) * 16 + slot * 4;
            __half hx = __float2half_rn(sa[i].x), hy = __float2half_rn(sa[i].y);
            __half hz = __float2half_rn(sa[i].z), hw = __float2half_rn(sa[i].w);
            *(__half2*)(base + aoff)      = __halves2half2(hx, hy);
            *(__half2*)(base + aoff + 16) = __halves2half2(hz, hw);
            __half lx = __float2half_rn(sa[i].x - __half2float(hx));
            __half ly = __float2half_rn(sa[i].y - __half2float(hy));
            __half lz = __float2half_rn(sa[i].z - __half2float(hz));
            __half lw = __float2half_rn(sa[i].w - __half2float(hw));
            *(__half2*)(base + AMAT_B + aoff)      = __halves2half2(lx, ly);
            *(__half2*)(base + AMAT_B + aoff + 16) = __halves2half2(lz, lw);
            int boff = ((m >> 3) * 2 + k16) * BREG_B + ((m & 7) * 4 + tg0) * 8 + ((kk >= 8) ? 4 : 0);
            char* Bh = base + 2 * AMAT_B;
            char* Bl = Bh + BMAT_B;
            *(uint32_t*)(Bh + boff)     = sbh[i].x;
            *(uint32_t*)(Bh + boff + 8) = sbh[i].y;
            *(uint32_t*)(Bl + boff)     = sbl[i].x;
            *(uint32_t*)(Bl + boff + 8) = sbl[i].y;
        }
    };

    auto do_comp = [&](int s) {
        const char* base = stg + s * STG_B;
#pragma unroll
        for (int k16 = 0; k16 < 2; k16++) {
            uint4 ah[2], al[2];
#pragma unroll
            for (int tm = 0; tm < 2; tm++) {
                int m16 = wm * 2 + tm;
                const char* pA = base + (m16 * 2 + k16) * AREG_B + lane * 16;
                ah[tm] = *(const uint4*)pA;
                al[tm] = *(const uint4*)(pA + AMAT_B);
            }
#pragma unroll
            for (int tn = 0; tn < 4; tn++) {
                int n8 = wn * 4 + tn;
                const char* pB = base + 2 * AMAT_B + (n8 * 2 + k16) * BREG_B + lane * 8;
                uint2 bh = *(const uint2*)pB;
                uint2 bl = *(const uint2*)(pB + BMAT_B);
#pragma unroll
                for (int tm = 0; tm < 2; tm++) {
                    mma16(acc[tm][tn], ah[tm], bh);
                    mma16(acc[tm][tn], al[tm], bh);
                    mma16(acc[tm][tn], ah[tm], bl);
                }
            }
        }
    };

    const int NIT = K >> 5;
    do_ldg();
    do_sts(0);
    __syncthreads();
    for (int it = 0; it < NIT; it++) {
        if (it + 1 < NIT) do_ldg();
        do_comp(it & 1);
        if (it + 1 < NIT) do_sts((it + 1) & 1);
        __syncthreads();
    }

#pragma unroll
    for (int tm = 0; tm < 2; tm++) {
        int r0 = wm * 32 + tm * 16 + g;
        float s0 = rs_s[r0], s1 = rs_s[r0 + 8];
        size_t o0 = (size_t)ridx_s[r0] * HID;
        size_t o1 = (size_t)ridx_s[r0 + 8] * HID;
#pragma unroll
        for (int tn = 0; tn < 4; tn++) {
            int n0 = nb * 128 + wn * 32 + tn * 8 + 2 * tg;
            *(float2*)(C + o0 + n0) = make_float2(acc[tm][tn][0] * s0, acc[tm][tn][1] * s0);
            *(float2*)(C + o1 + n0) = make_float2(acc[tm][tn][2] * s1, acc[tm][tn][3] * s1);
        }
    }
}

// ---- coalesced transpose + fp16-split ---------------------------------------
__global__ void k_wsplitT(const float* __restrict__ W, __half* __restrict__ hi,
                          __half* __restrict__ lo, int K, int N) {
    __shared__ float tile[32][33];
    int kb = blockIdx.y * 32, nb = blockIdx.x * 32;
    int tx = threadIdx.x, ty = threadIdx.y;
#pragma unroll
    for (int r = ty; r < 32; r += 8)
        tile[r][tx] = W[(size_t)(kb + r) * N + nb + tx];
    __syncthreads();
#pragma unroll
    for (int r = ty; r < 32; r += 8) {
        float v = tile[tx][r];
        __half h = __float2half_rn(v);
        size_t o = (size_t)(nb + r) * K + kb + tx;
        hi[o] = h;
        lo[o] = __float2half_rn(v - __half2float(h));
    }
}

// ---------------- graph preprocessing ---------------------------------------
__global__ void k_init() {
    int i = blockIdx.x * blockDim.x + threadIdx.x;
    if (i < NN) { g_cnt[i] = 0; g_nmask[i] = 1.f; g_rows[i] = 1.f; g_iota[i] = i; }
}

__global__ void k_count(const int* __restrict__ dst) {
    int e = blockIdx.x * blockDim.x + threadIdx.x;
    if (e < EE) atomicAdd(&g_cnt[dst[e]], 1);
}

__global__ void k_scan() {
    __shared__ int part[1024];
    int t = threadIdx.x;
    int base = t * 32;
    int s = 0;
#pragma unroll
    for (int i = 0; i < 32; i++) s += g_cnt[base + i];
    part[t] = s;
    __syncthreads();
    for (int off = 1; off < 1024; off <<= 1) {
        int v = (t >= off) ? part[t - off] : 0;
        __syncthreads();
        part[t] += v;
        __syncthreads();
    }
    int run = (t == 0) ? 0 : part[t - 1];
#pragma unroll
    for (int i = 0; i < 32; i++) {
        int c = g_cnt[base + i];
        g_off[base + i] = run;
        g_cur[base + i] = run;
        g_dinv[base + i] = rsqrtf((float)c + 1.f);
        run += c;
    }
    if (t == 1023) g_off[NN] = run;
}

__global__ void k_scatter(const int* __restrict__ src, const int* __restrict__ dst) {
    int e = blockIdx.x * blockDim.x + threadIdx.x;
    if (e < EE) {
        int p = atomicAdd(&g_cur[dst[e]], 1);
        g_csr[p] = src[e];
    }
}

// ---- agg + lrelu + fused pool dots; active-neighbor compaction -------------
__global__ void k_agg(const float* __restrict__ bias, const float* __restrict__ wr,
                      const float* __restrict__ wo, int dopool,
                      const int* __restrict__ map) {
    __shared__ float s_ds[128];
    __shared__ int   s_src[128];
    __shared__ float s2[8];
    __shared__ int   s_cnt;
    int v = map[blockIdx.x];
    int c = threadIdx.x;
    int lane = c & 31;
    float dv = g_dinv[v];
    int e0 = g_off[v], deg = g_off[v + 1] - e0;

    float4 a = make_float4(0.f, 0.f, 0.f, 0.f);
    for (int base = 0; base < deg; base += 128) {
        int n = deg - base; if (n > 128) n = 128;
        if (c == 0) s_cnt = 0;
        __syncthreads();
        bool inb = c < n;
        int s = 0; float ds = 0.f;
        if (inb) { s = g_csr[e0 + base + c]; ds = g_dinv[s]; }
        bool act = inb && (ds != 0.f);
        unsigned m = __ballot_sync(0xffffffffu, act);
        int rank = __popc(m & ((1u << lane) - 1));
        int wbase = 0;
        if (lane == 0) wbase = atomicAdd(&s_cnt, __popc(m));
        wbase = __shfl_sync(0xffffffffu, wbase, 0);
        if (act) { s_src[wbase + rank] = s; s_ds[wbase + rank] = ds; }
        __syncthreads();
        int nact = s_cnt;
        int i = 0;
        for (; i + 2 <= nact; i += 2) {
            float ds0 = s_ds[i],   ds1 = s_ds[i + 1];
            float4 t0 = *((const float4*)(g_t + (size_t)s_src[i]     * HID) + c);
            float4 t1 = *((const float4*)(g_t + (size_t)s_src[i + 1] * HID) + c);
            a.x += ds0 * t0.x + ds1 * t1.x;
            a.y += ds0 * t0.y + ds1 * t1.y;
            a.z += ds0 * t0.z + ds1 * t1.z;
            a.w += ds0 * t0.w + ds1 * t1.w;
        }
        if (i < nact) {
            float ds0 = s_ds[i];
            float4 t0 = *((const float4*)(g_t + (size_t)s_src[i] * HID) + c);
            a.x += ds0 * t0.x; a.y += ds0 * t0.y;
            a.z += ds0 * t0.z; a.w += ds0 * t0.w;
        }
        __syncthreads();
    }

    float4 tv = *((const float4*)(g_t + (size_t)v * HID) + c);
    float4 bi = *((const float4*)bias + c);
    float dv2 = dv * dv;
    float4 h;
    h.x = lrelu(dv * a.x + dv2 * tv.x + bi.x);
    h.y = lrelu(dv * a.y + dv2 * tv.y + bi.y);
    h.z = lrelu(dv * a.z + dv2 * tv.z + bi.z);
    h.w = lrelu(dv * a.w + dv2 * tv.w + bi.w);
    *((float4*)(g_h + (size_t)v * HID) + c) = h;

    if (dopool) {
        float4 r4 = *((const float4*)wr + c);
        float4 o4 = *((const float4*)wo + c);
        float pr = h.x * r4.x + h.y * r4.y + h.z * r4.z + h.w * r4.w;
        float po = h.x * o4.x + h.y * o4.y + h.z * o4.z + h.w * o4.w;
#pragma unroll
        for (int o = 16; o > 0; o >>= 1) {
            pr += __shfl_down_sync(0xffffffff, pr, o);
            po += __shfl_down_sync(0xffffffff, po, o);
        }
        int wd = c >> 5;
        if (lane == 0) { s2[wd * 2] = pr; s2[wd * 2 + 1] = po; }
        __syncthreads();
        if (c == 0) {
            g_sr[v] = s2[0] + s2[2] + s2[4] + s2[6];
            g_so[v] = s2[1] + s2[3] + s2[5] + s2[7];
        }
    }
}

// ---- per-graph score (nodebase = g*NPG) ------------------------------------
__global__ void k_score(const float* __restrict__ br, int nodebase) {
    int v = nodebase + blockIdx.x * blockDim.x + threadIdx.x;
    if (g_nmask[v] <= 0.f) { g_score[v] = -1e30f; return; }
    float s = br[0] + g_so[v];
    int e0 = g_off[v], e1 = g_off[v + 1];
    for (int i = e0; i < e1; i++) s += g_sr[g_csr[i]];
    g_score[v] = s;
}

// ---- per-graph next-layer deg ----------------------------------------------
__global__ void k_deg(int nodebase) {
    int v = nodebase + blockIdx.x * blockDim.x + threadIdx.x;
    if (g_nmask[v] <= 0.f) { g_dinv[v] = 0.f; return; }
    float s = 1.f;
    int e0 = g_off[v], e1 = g_off[v + 1];
    for (int i = e0; i < e1; i++) s += g_nmask[g_csr[i]];
    g_dinv[v] = rsqrtf(s);
}

// ---- per-graph: radix-select topk + mask/rows/sr-zero + ordered compact ----
__global__ void __launch_bounds__(1024)
k_topk(int gph, int kkeep, int* __restrict__ ridx) {
    __shared__ float    sc[NPG];
    __shared__ unsigned key[NPG];
    __shared__ int hist[256];
    __shared__ int sfx[256];
    __shared__ int wsum[32];
    __shared__ int s_bin, s_remk;
    __shared__ unsigned s_pref;
    int t = threadIdx.x;
    int base = gph * NPG;

    for (int i = t; i < NPG; i += 1024) {
        float s = g_score[base + i];
        sc[i] = s;
        unsigned u = __float_as_uint(s);
        key[i] = (u & 0x80000000u) ? ~u : (u | 0x80000000u);
    }
    if (t == 0) { s_remk = kkeep; s_pref = 0u; }
    __syncthreads();

    for (int shift = 24; shift >= 0; shift -= 8) {
        if (t < 256) hist[t] = 0;
        __syncthreads();
        unsigned pref = s_pref;
        int remk = s_remk;
        for (int i = t; i < NPG; i += 1024) {
            unsigned u = key[i];
            bool ok = (shift == 24) || ((u >> (shift + 8)) == pref);
            if (ok) atomicAdd(&hist[(u >> shift) & 255], 1);
        }
        __syncthreads();
        if (t < 256) sfx[t] = hist[t];
        __syncthreads();
        for (int off = 1; off < 256; off <<= 1) {
            int v2 = 0;
            if (t < 256 && t + off < 256) v2 = sfx[t + off];
            __syncthreads();
            if (t < 256) sfx[t] += v2;
            __syncthreads();
        }
        if (t < 256) {
            int excl = (t < 255) ? sfx[t + 1] : 0;
            if (excl < remk && remk <= excl + hist[t]) {
                s_bin = t;
                s_remk = remk - excl;
            }
        }
        __syncthreads();
        if (t == 0) s_pref = (s_pref << 8) | (unsigned)s_bin;
        __syncthreads();
    }
    unsigned Tkey = s_pref;

    for (int i = t; i < NPG; i += 1024) {
        int v = base + i;
        float keep = (key[i] >= Tkey) ? 1.f : 0.f;
        g_nmask[v] = keep;
        g_rows[v] = keep * tanhf(sc[i]);
        if (keep == 0.f) g_sr[v] = 0.f;
        sc[i] = keep;
    }
    __syncthreads();

    int k4 = t * 4;
    int cnt = 0;
#pragma unroll
    for (int j = 0; j < 4; j++) cnt += (sc[k4 + j] > 0.f) ? 1 : 0;
    int lane_ = t & 31, w_ = t >> 5;
    int x = cnt;
#pragma unroll
    for (int o = 1; o < 32; o <<= 1) {
        int y = __shfl_up_sync(0xffffffff, x, o);
        if (lane_ >= o) x += y;
    }
    if (lane_ == 31) wsum[w_] = x;
    __syncthreads();
    if (w_ == 0) {
        int y = wsum[lane_];
#pragma unroll
        for (int o = 1; o < 32; o <<= 1) {
            int z = __shfl_up_sync(0xffffffff, y, o);
            if (lane_ >= o) y += z;
        }
        wsum[lane_] = y;
    }
    __syncthreads();
    int pos = x - cnt + (w_ ? wsum[w_ - 1] : 0);
#pragma unroll
    for (int j = 0; j < 4; j++) {
        if (sc[k4 + j] > 0.f) { ridx[gph * kkeep + pos] = base + k4 + j; pos++; }
    }
}

// ---------------- readout (per graph) ----------------------------------------
__global__ void k_pool1(int g, const int* __restrict__ ridx3) {   // grid = 16
    int ch = blockIdx.x, c = threadIdx.x;
    const int* rp = ridx3 + g * K2 + ch * 64;
    float sum = 0.f, mx = -3.4e38f;
    for (int n = 0; n < 64; n++) {
        int node = rp[n];
        float h = g_h[(size_t)node * HID + c];
        sum += h;
        mx = fmaxf(mx, h);
    }
    g_pp_sum[(size_t)(g * 16 + ch) * HID + c] = sum;
    g_pp_max[(size_t)(g * 16 + ch) * HID + c] = mx;
}

__global__ void __launch_bounds__(512)
k_head(int g, const float* __restrict__ fc1w, const float* __restrict__ fc1b,
       const float* __restrict__ fc2w, const float* __restrict__ fc2b,
       float* __restrict__ out) {
    __shared__ float gp[2 * HID];
    __shared__ float f1[HID];
    int c = threadIdx.x;

    float sum = 0.f, mx = -3.4e38f;
    for (int j = 0; j < 16; j++) {
        sum += g_pp_sum[(size_t)(g * 16 + j) * HID + c];
        mx = fmaxf(mx, g_pp_max[(size_t)(g * 16 + j) * HID + c]);
    }
    gp[c] = sum / (float)K2;
    gp[HID + c] = mx;
    __syncthreads();

    float s = fc1b[c];
    for (int k = 0; k < 2 * HID; k++) s = fmaf(gp[k], fc1w[k * HID + c], s);
    f1[c] = lrelu(s);
    __syncthreads();

    if (c < NCLS) {
        float o = fc2b[c];
        for (int k = 0; k < HID; k++) o = fmaf(f1[k], fc2w[k * NCLS + c], o);
        out[g * NCLS + c] = o;
    }
}

// ---------------- launch -----------------------------------------------------
extern "C" void kernel_launch(void* const* d_in, const int* in_sizes, int n_in,
                              void* d_out, int out_size) {
    const float* x     = (const float*)d_in[0];
    const int*   esrc  = (const int*)d_in[1];
    const int*   edst  = (const int*)d_in[2];
    const float* W1    = (const float*)d_in[3];
    const float* b1    = (const float*)d_in[4];
    const float* p1wr  = (const float*)d_in[5];
    const float* p1br  = (const float*)d_in[6];
    const float* p1wo  = (const float*)d_in[7];
    const float* W2    = (const float*)d_in[8];
    const float* b2    = (const float*)d_in[9];
    const float* p2wr  = (const float*)d_in[10];
    const float* p2br  = (const float*)d_in[11];
    const float* p2wo  = (const float*)d_in[12];
    const float* W3    = (const float*)d_in[13];
    const float* b3    = (const float*)d_in[14];
    const float* fc1w  = (const float*)d_in[15];
    const float* fc1b  = (const float*)d_in[16];
    const float* fc2w  = (const float*)d_in[17];
    const float* fc2b  = (const float*)d_in[18];
    float* out = (float*)d_out;

    float*  dT;     cudaGetSymbolAddress((void**)&dT, g_t);
    float*  dH;     cudaGetSymbolAddress((void**)&dH, g_h);
    float*  dRS;    cudaGetSymbolAddress((void**)&dRS, g_rows);
    __half* dW1hi;  cudaGetSymbolAddress((void**)&dW1hi, g_w1t_hi);
    __half* dW1lo;  cudaGetSymbolAddress((void**)&dW1lo, g_w1t_lo);
    __half* dW2hi;  cudaGetSymbolAddress((void**)&dW2hi, g_w2t_hi);
    __half* dW2lo;  cudaGetSymbolAddress((void**)&dW2lo, g_w2t_lo);
    __half* dW3hi;  cudaGetSymbolAddress((void**)&dW3hi, g_w3t_hi);
    __half* dW3lo;  cudaGetSymbolAddress((void**)&dW3lo, g_w3t_lo);
    int*    dIota;  cudaGetSymbolAddress((void**)&dIota, g_iota);
    int*    dR2;    cudaGetSymbolAddress((void**)&dR2, g_ridx2);
    int*    dR3;    cudaGetSymbolAddress((void**)&dR3, g_ridx3);

    // same resource budget as passing R11: 1 extra stream + a few events
    static cudaStream_t s_side = 0;
    static cudaEvent_t  e_fork = 0, e_w1 = 0, e_side = 0, e_join = 0;
    static int cfg_done = 0;
    if (!cfg_done) {   // first (non-captured) call only; host-side config
        cudaFuncSetAttribute(mma_gemm, cudaFuncAttributeMaxDynamicSharedMemorySize, SM_BYTES);
        cudaStreamCreateWithFlags(&s_side, cudaStreamNonBlocking);
        cudaEventCreateWithFlags(&e_fork, cudaEventDisableTiming);
        cudaEventCreateWithFlags(&e_w1,   cudaEventDisableTiming);
        cudaEventCreateWithFlags(&e_side, cudaEventDisableTiming);
        cudaEventCreateWithFlags(&e_join, cudaEventDisableTiming);
        cfg_done = 1;
    }

    // per-graph chain (stages after GEMM1; CSR + weights must be ready)
    auto chain = [&](cudaStream_t sg, int g) {
        k_agg<<<NPG, 128, 0, sg>>>(b1, p1wr, p1wo, 1, dIota + g * NPG);
        k_score<<<NPG / 256, 256, 0, sg>>>(p1br, g * NPG);
        k_topk<<<1, 1024, 0, sg>>>(g, K1, dR2);
        k_deg<<<NPG / 256, 256, 0, sg>>>(g * NPG);
        mma_gemm<<<dim3(HID / 128, K1 / 128), 512, SM_BYTES, sg>>>(
            dH, dW2hi, dW2lo, dRS, dR2 + g * K1, dT, HID);
        k_agg<<<K1, 128, 0, sg>>>(b2, p2wr, p2wo, 1, dR2 + g * K1);
        k_score<<<NPG / 256, 256, 0, sg>>>(p2br, g * NPG);
        k_topk<<<1, 1024, 0, sg>>>(g, K2, dR3);
        k_deg<<<NPG / 256, 256, 0, sg>>>(g * NPG);
        mma_gemm<<<dim3(HID / 128, K2 / 128), 512, SM_BYTES, sg>>>(
            dH, dW3hi, dW3lo, dRS, dR3 + g * K2, dT, HID);
        k_agg<<<K2, 128, 0, sg>>>(b3, (const float*)0, (const float*)0, 0, dR3 + g * K2);
        k_pool1<<<16, HID, 0, sg>>>(g, dR3);
        k_head<<<1, HID, 0, sg>>>(g, fc1w, fc1b, fc2w, fc2b, out);
    };

    // ---- shared preprocessing, forked ----
    k_init<<<NN / 256, 256>>>();
    cudaEventRecord(e_fork, 0);
    cudaStreamWaitEvent(s_side, e_fork, 0);

    // side: CSR build + W2/W3 splits
    k_count<<<EE / 256, 256, 0, s_side>>>(edst);
    k_scan<<<1, 1024, 0, s_side>>>();
    k_scatter<<<EE / 256, 256, 0, s_side>>>(esrc, edst);
    k_wsplitT<<<dim3(HID / 32, HID / 32), dim3(32, 8), 0, s_side>>>(W2, dW2hi, dW2lo, HID, HID);
    k_wsplitT<<<dim3(HID / 32, HID / 32), dim3(32, 8), 0, s_side>>>(W3, dW3hi, dW3lo, HID, HID);
    cudaEventRecord(e_side, s_side);

    // main: W1 split (needed by all GEMM1s)
    k_wsplitT<<<dim3(HID / 32, INC / 32), dim3(32, 8)>>>(W1, dW1hi, dW1lo, INC, HID);
    cudaEventRecord(e_w1, 0);

    // ---- pipeline A (main): graphs 0-3 ----
    for (int g = 0; g < 4; g++)
        mma_gemm<<<dim3(HID / 128, NPG / 128), 512, SM_BYTES>>>(
            x, dW1hi, dW1lo, dRS, dIota + g * NPG, dT, INC);
    cudaStreamWaitEvent(0, e_side, 0);
    for (int g = 0; g < 4; g++) chain(0, g);

    // ---- pipeline B (side): graphs 4-7 ----
    cudaStreamWaitEvent(s_side, e_w1, 0);
    for (int g = 4; g < 8; g++)
        mma_gemm<<<dim3(HID / 128, NPG / 128), 512, SM_BYTES, s_side>>>(
            x, dW1hi, dW1lo, dRS, dIota + g * NPG, dT, INC);
    for (int g = 4; g < 8; g++) chain(s_side, g);
    cudaEventRecord(e_join, s_side);

    // join
    cudaStreamWaitEvent(0, e_join, 0);
}

// round 14
// speedup vs baseline: 1.4850x; 1.4850x over previous
#include <cuda_runtime.h>
#include <cuda_fp16.h>
#include <math.h>
#include <stdint.h>

#define BB    8
#define NPG   4096
#define NN    32768
#define EE    262144
#define INC   1024
#define HID   512
#define NCLS  4
#define K1    2048
#define K2    1024
#define NACT2 (BB*K1)
#define NACT3 (BB*K2)

// ---------------- scratch (device globals; no allocations allowed) ----------
__device__ float g_t[NN * HID];
__device__ float g_h[NN * HID];
__device__ float g_dinv[NN];
__device__ float g_nmask[NN];
__device__ float g_rows[NN];
__device__ float g_sr[NN];
__device__ float g_so[NN];
__device__ float g_score[NN];
__device__ int   g_cnt[NN];
__device__ int   g_off[NN + 1];
__device__ int   g_cur[NN];
__device__ int   g_csr[EE];
__device__ __half g_w1t_hi[HID * INC];
__device__ __half g_w1t_lo[HID * INC];
__device__ __half g_w2t_hi[HID * HID];
__device__ __half g_w2t_lo[HID * HID];
__device__ __half g_w3t_hi[HID * HID];
__device__ __half g_w3t_lo[HID * HID];
__device__ int   g_iota[NN];
__device__ int   g_ridx2[NACT2 + 64];
__device__ int   g_ridx3[NACT3 + 64];
__device__ float g_pp_sum[BB * 16 * HID];
__device__ float g_pp_max[BB * 16 * HID];

__device__ __forceinline__ float lrelu(float x) { return x > 0.f ? x : 0.01f * x; }

// ---------------- fp16 m16n8k16 mma (base-target PTX, sm_80+) ---------------
__device__ __forceinline__ void mma16(float* c, uint4 a, uint2 b) {
    asm volatile(
        "mma.sync.aligned.m16n8k16.row.col.f32.f16.f16.f32 "
        "{%0,%1,%2,%3}, {%4,%5,%6,%7}, {%8,%9}, {%0,%1,%2,%3};"
        : "+f"(c[0]), "+f"(c[1]), "+f"(c[2]), "+f"(c[3])
        : "r"(a.x), "r"(a.y), "r"(a.z), "r"(a.w), "r"(b.x), "r"(b.y));
}

// ======= fp16x3 HMMA GEMM: block 128x128, BK=32, 512 thr (16 warps 4x4) =====
#define AREG_B   576
#define AMAT_B   (16 * AREG_B)
#define BREG_B   296
#define BMAT_B   (32 * BREG_B)
#define STG_B    (2*AMAT_B + 2*BMAT_B)
#define SM_BYTES (1024 + 2 * STG_B)         /* 75776 */

__global__ void __launch_bounds__(512, 1)
mma_gemm(const float* __restrict__ A, const __half* __restrict__ Bhi,
         const __half* __restrict__ Blo, const float* __restrict__ rs,
         const int* __restrict__ ridx, float* __restrict__ C, int K)
{
    extern __shared__ char smc[];
    int*   ridx_s = (int*)smc;
    float* rs_s   = (float*)(smc + 512);
    char*  stg    = smc + 1024;

    int tid = threadIdx.x;
    int lane = tid & 31, wid = tid >> 5;
    int g = lane >> 2, tg = lane & 3;
    int wm = wid & 3, wn = wid >> 2;
    int nb = blockIdx.x, mb = blockIdx.y;

    if (tid < 128) {
        int r = ridx[mb * 128 + tid];
        ridx_s[tid] = r;
        rs_s[tid] = rs[r];
    }
    __syncthreads();

    float acc[2][4][4];
#pragma unroll
    for (int a = 0; a < 2; a++)
#pragma unroll
        for (int b = 0; b < 4; b++)
#pragma unroll
            for (int q = 0; q < 4; q++) acc[a][b][q] = 0.f;

    int jm[2], jc[2];
    const float* pa[2];
    const __half *pbh[2], *pbl[2];
#pragma unroll
    for (int i = 0; i < 2; i++) {
        int j = tid + 512 * i;
        jm[i] = j >> 3; jc[i] = (j & 7) * 4;
        pa[i]  = A   + (size_t)ridx_s[jm[i]] * K + jc[i];
        pbh[i] = Bhi + (size_t)(nb * 128 + jm[i]) * K + jc[i];
        pbl[i] = Blo + (size_t)(nb * 128 + jm[i]) * K + jc[i];
    }

    float4 sa[2];
    uint2  sbh[2], sbl[2];

    auto do_ldg = [&]() {
#pragma unroll
        for (int i = 0; i < 2; i++) {
            sa[i]  = *(const float4*)pa[i];  pa[i]  += 32;
            sbh[i] = *(const uint2*)pbh[i]; pbh[i] += 32;
            sbl[i] = *(const uint2*)pbl[i]; pbl[i] += 32;
        }
    };

    auto do_sts = [&](int s) {
        char* base = stg + s * STG_B;
#pragma unroll
        for (int i = 0; i < 2; i++) {
            int m = jm[i], c4 = jc[i];
            int k16 = c4 >> 4, kk = c4 & 15;
            int tg0 = (kk >> 1) & 3;
            int slot = ((kk >= 8) ? 2 : 0) + ((m & 15) >> 3);
            int aoff = ((m >> 4) * 2 + k16) * AREG_B + ((m & 7) * 4 + tg0) * 16 + slot * 4;
            __half hx = __float2half_rn(sa[i].x), hy = __float2half_rn(sa[i].y);
            __half hz = __float2half_rn(sa[i].z), hw = __float2half_rn(sa[i].w);
            *(__half2*)(base + aoff)      = __halves2half2(hx, hy);
            *(__half2*)(base + aoff + 16) = __halves2half2(hz, hw);
            __half lx = __float2half_rn(sa[i].x - __half2float(hx));
            __half ly = __float2half_rn(sa[i].y - __half2float(hy));
            __half lz = __float2half_rn(sa[i].z - __half2float(hz));
            __half lw = __float2half_rn(sa[i].w - __half2float(hw));
            *(__half2*)(base + AMAT_B + aoff)      = __halves2half2(lx, ly);
            *(__half2*)(base + AMAT_B + aoff + 16) = __halves2half2(lz, lw);
            int boff = ((m >> 3) * 2 + k16) * BREG_B + ((m & 7) * 4 + tg0) * 8 + ((kk >= 8) ? 4 : 0);
            char* Bh = base + 2 * AMAT_B;
            char* Bl = Bh + BMAT_B;
            *(uint32_t*)(Bh + boff)     = sbh[i].x;
            *(uint32_t*)(Bh + boff + 8) = sbh[i].y;
            *(uint32_t*)(Bl + boff)     = sbl[i].x;
            *(uint32_t*)(Bl + boff + 8) = sbl[i].y;
        }
    };

    auto do_comp = [&](int s) {
        const char* base = stg + s * STG_B;
#pragma unroll
        for (int k16 = 0; k16 < 2; k16++) {
            uint4 ah[2], al[2];
#pragma unroll
            for (int tm = 0; tm < 2; tm++) {
                int m16 = wm * 2 + tm;
                const char* pA = base + (m16 * 2 + k16) * AREG_B + lane * 16;
                ah[tm] = *(const uint4*)pA;
                al[tm] = *(const uint4*)(pA + AMAT_B);
            }
#pragma unroll
            for (int tn = 0; tn < 4; tn++) {
                int n8 = wn * 4 + tn;
                const char* pB = base + 2 * AMAT_B + (n8 * 2 + k16) * BREG_B + lane * 8;
                uint2 bh = *(const uint2*)pB;
                uint2 bl = *(const uint2*)(pB + BMAT_B);
#pragma unroll
                for (int tm = 0; tm < 2; tm++) {
                    mma16(acc[tm][tn], ah[tm], bh);
                    mma16(acc[tm][tn], al[tm], bh);
                    mma16(acc[tm][tn], ah[tm], bl);
                }
            }
        }
    };

    const int NIT = K >> 5;
    do_ldg();
    do_sts(0);
    __syncthreads();
    for (int it = 0; it < NIT; it++) {
        if (it + 1 < NIT) do_ldg();
        do_comp(it & 1);
        if (it + 1 < NIT) do_sts((it + 1) & 1);
        __syncthreads();
    }

#pragma unroll
    for (int tm = 0; tm < 2; tm++) {
        int r0 = wm * 32 + tm * 16 + g;
        float s0 = rs_s[r0], s1 = rs_s[r0 + 8];
        size_t o0 = (size_t)ridx_s[r0] * HID;
        size_t o1 = (size_t)ridx_s[r0 + 8] * HID;
#pragma unroll
        for (int tn = 0; tn < 4; tn++) {
            int n0 = nb * 128 + wn * 32 + tn * 8 + 2 * tg;
            *(float2*)(C + o0 + n0) = make_float2(acc[tm][tn][0] * s0, acc[tm][tn][1] * s0);
            *(float2*)(C + o1 + n0) = make_float2(acc[tm][tn][2] * s1, acc[tm][tn][3] * s1);
        }
    }
}

// ---- coalesced transpose + fp16-split ---------------------------------------
__global__ void k_wsplitT(const float* __restrict__ W, __half* __restrict__ hi,
                          __half* __restrict__ lo, int K, int N) {
    __shared__ float tile[32][33];
    int kb = blockIdx.y * 32, nb = blockIdx.x * 32;
    int tx = threadIdx.x, ty = threadIdx.y;
#pragma unroll
    for (int r = ty; r < 32; r += 8)
        tile[r][tx] = W[(size_t)(kb + r) * N + nb + tx];
    __syncthreads();
#pragma unroll
    for (int r = ty; r < 32; r += 8) {
        float v = tile[tx][r];
        __half h = __float2half_rn(v);
        size_t o = (size_t)(nb + r) * K + kb + tx;
        hi[o] = h;
        lo[o] = __float2half_rn(v - __half2float(h));
    }
}

// ---- W2+W3 in one launch (blockIdx.z selects) -------------------------------
__global__ void k_wsplitT2(const float* __restrict__ Wa, __half* __restrict__ hia,
                           __half* __restrict__ loa, const float* __restrict__ Wb,
                           __half* __restrict__ hib, __half* __restrict__ lob) {
    __shared__ float tile[32][33];
    const float* W = blockIdx.z ? Wb : Wa;
    __half* hi = blockIdx.z ? hib : hia;
    __half* lo = blockIdx.z ? lob : loa;
    int kb = blockIdx.y * 32, nb = blockIdx.x * 32;
    int tx = threadIdx.x, ty = threadIdx.y;
#pragma unroll
    for (int r = ty; r < 32; r += 8)
        tile[r][tx] = W[(size_t)(kb + r) * HID + nb + tx];
    __syncthreads();
#pragma unroll
    for (int r = ty; r < 32; r += 8) {
        float v = tile[tx][r];
        __half h = __float2half_rn(v);
        size_t o = (size_t)(nb + r) * HID + kb + tx;
        hi[o] = h;
        lo[o] = __float2half_rn(v - __half2float(h));
    }
}

// ---------------- graph preprocessing ---------------------------------------
__global__ void k_init() {
    int i = blockIdx.x * blockDim.x + threadIdx.x;
    if (i < NN) { g_cnt[i] = 0; g_nmask[i] = 1.f; g_rows[i] = 1.f; g_iota[i] = i; }
}

__global__ void k_count(const int* __restrict__ dst) {
    int e = blockIdx.x * blockDim.x + threadIdx.x;
    if (e < EE) atomicAdd(&g_cnt[dst[e]], 1);
}

__global__ void k_scan() {   // CSR offsets + layer-1 dinv
    __shared__ int part[1024];
    int t = threadIdx.x;
    int base = t * 32;
    int s = 0;
#pragma unroll
    for (int i = 0; i < 32; i++) s += g_cnt[base + i];
    part[t] = s;
    __syncthreads();
    for (int off = 1; off < 1024; off <<= 1) {
        int v = (t >= off) ? part[t - off] : 0;
        __syncthreads();
        part[t] += v;
        __syncthreads();
    }
    int run = (t == 0) ? 0 : part[t - 1];
#pragma unroll
    for (int i = 0; i < 32; i++) {
        int c = g_cnt[base + i];
        g_off[base + i] = run;
        g_cur[base + i] = run;
        g_dinv[base + i] = rsqrtf((float)c + 1.f);
        run += c;
    }
    if (t == 1023) g_off[NN] = run;
}

__global__ void k_scatter(const int* __restrict__ src, const int* __restrict__ dst) {
    int e = blockIdx.x * blockDim.x + threadIdx.x;
    if (e < EE) {
        int p = atomicAdd(&g_cur[dst[e]], 1);
        g_csr[p] = src[e];
    }
}

// ---- agg + lrelu + fused pool dots; optional active-neighbor compaction ----
__global__ void k_agg(const float* __restrict__ bias, const float* __restrict__ wr,
                      const float* __restrict__ wo, int dopool, int allact,
                      const int* __restrict__ map) {
    __shared__ float s_ds[128];
    __shared__ int   s_src[128];
    __shared__ float s2[8];
    __shared__ int   s_cnt;
    int v = map[blockIdx.x];
    int c = threadIdx.x;
    int lane = c & 31;
    float dv = g_dinv[v];
    int e0 = g_off[v], deg = g_off[v + 1] - e0;

    float4 a = make_float4(0.f, 0.f, 0.f, 0.f);
    for (int base = 0; base < deg; base += 128) {
        int n = deg - base; if (n > 128) n = 128;
        int nact;
        if (allact) {
            // layer 1: every neighbor active, no compaction needed
            if (c < n) {
                int s = g_csr[e0 + base + c];
                s_src[c] = s;
                s_ds[c] = g_dinv[s];
            }
            nact = n;
            __syncthreads();
        } else {
            if (c == 0) s_cnt = 0;
            __syncthreads();
            bool inb = c < n;
            int s = 0; float ds = 0.f;
            if (inb) { s = g_csr[e0 + base + c]; ds = g_dinv[s]; }
            bool act = inb && (ds != 0.f);
            unsigned m = __ballot_sync(0xffffffffu, act);
            int rank = __popc(m & ((1u << lane) - 1));
            int wbase = 0;
            if (lane == 0) wbase = atomicAdd(&s_cnt, __popc(m));
            wbase = __shfl_sync(0xffffffffu, wbase, 0);
            if (act) { s_src[wbase + rank] = s; s_ds[wbase + rank] = ds; }
            __syncthreads();
            nact = s_cnt;
        }
        int i = 0;
        for (; i + 2 <= nact; i += 2) {
            float ds0 = s_ds[i],   ds1 = s_ds[i + 1];
            float4 t0 = *((const float4*)(g_t + (size_t)s_src[i]     * HID) + c);
            float4 t1 = *((const float4*)(g_t + (size_t)s_src[i + 1] * HID) + c);
            a.x += ds0 * t0.x + ds1 * t1.x;
            a.y += ds0 * t0.y + ds1 * t1.y;
            a.z += ds0 * t0.z + ds1 * t1.z;
            a.w += ds0 * t0.w + ds1 * t1.w;
        }
        if (i < nact) {
            float ds0 = s_ds[i];
            float4 t0 = *((const float4*)(g_t + (size_t)s_src[i] * HID) + c);
            a.x += ds0 * t0.x; a.y += ds0 * t0.y;
            a.z += ds0 * t0.z; a.w += ds0 * t0.w;
        }
        __syncthreads();
    }

    float4 tv = *((const float4*)(g_t + (size_t)v * HID) + c);
    float4 bi = *((const float4*)bias + c);
    float dv2 = dv * dv;
    float4 h;
    h.x = lrelu(dv * a.x + dv2 * tv.x + bi.x);
    h.y = lrelu(dv * a.y + dv2 * tv.y + bi.y);
    h.z = lrelu(dv * a.z + dv2 * tv.z + bi.z);
    h.w = lrelu(dv * a.w + dv2 * tv.w + bi.w);
    *((float4*)(g_h + (size_t)v * HID) + c) = h;

    if (dopool) {
        float4 r4 = *((const float4*)wr + c);
        float4 o4 = *((const float4*)wo + c);
        float pr = h.x * r4.x + h.y * r4.y + h.z * r4.z + h.w * r4.w;
        float po = h.x * o4.x + h.y * o4.y + h.z * o4.z + h.w * o4.w;
#pragma unroll
        for (int o = 16; o > 0; o >>= 1) {
            pr += __shfl_down_sync(0xffffffff, pr, o);
            po += __shfl_down_sync(0xffffffff, po, o);
        }
        int wd = c >> 5;
        if (lane == 0) { s2[wd * 2] = pr; s2[wd * 2 + 1] = po; }
        __syncthreads();
        if (c == 0) {
            g_sr[v] = s2[0] + s2[2] + s2[4] + s2[6];
            g_so[v] = s2[1] + s2[3] + s2[5] + s2[7];
        }
    }
}

// ---- grid-wide score: dropped nodes have g_sr == 0 (zeroed in k_topk) ------
__global__ void k_score(const float* __restrict__ br) {
    int v = blockIdx.x * blockDim.x + threadIdx.x;
    if (v >= NN) return;
    if (g_nmask[v] <= 0.f) { g_score[v] = -1e30f; return; }
    float s = br[0] + g_so[v];
    int e0 = g_off[v], e1 = g_off[v + 1];
    for (int i = e0; i < e1; i++) s += g_sr[g_csr[i]];
    g_score[v] = s;
}

// ---- grid-wide next-layer deg ----------------------------------------------
__global__ void k_deg() {
    int v = blockIdx.x * blockDim.x + threadIdx.x;
    if (v >= NN) return;
    if (g_nmask[v] <= 0.f) { g_dinv[v] = 0.f; return; }
    float s = 1.f;
    int e0 = g_off[v], e1 = g_off[v + 1];
    for (int i = e0; i < e1; i++) s += g_nmask[g_csr[i]];
    g_dinv[v] = rsqrtf(s);
}

// ---- per-graph (batched over blockIdx.x): radix-select topk + compact ------
__global__ void __launch_bounds__(1024)
k_topk(int kkeep, int* __restrict__ ridx) {
    __shared__ float    sc[NPG];
    __shared__ unsigned key[NPG];
    __shared__ int hist[256];
    __shared__ int sfx[256];
    __shared__ int wsum[32];
    __shared__ int s_bin, s_remk;
    __shared__ unsigned s_pref;
    int gph = blockIdx.x, t = threadIdx.x;
    int base = gph * NPG;

    for (int i = t; i < NPG; i += 1024) {
        float s = g_score[base + i];
        sc[i] = s;
        unsigned u = __float_as_uint(s);
        key[i] = (u & 0x80000000u) ? ~u : (u | 0x80000000u);
    }
    if (t == 0) { s_remk = kkeep; s_pref = 0u; }
    __syncthreads();

    for (int shift = 24; shift >= 0; shift -= 8) {
        if (t < 256) hist[t] = 0;
        __syncthreads();
        unsigned pref = s_pref;
        int remk = s_remk;
        for (int i = t; i < NPG; i += 1024) {
            unsigned u = key[i];
            bool ok = (shift == 24) || ((u >> (shift + 8)) == pref);
            if (ok) atomicAdd(&hist[(u >> shift) & 255], 1);
        }
        __syncthreads();
        if (t < 256) sfx[t] = hist[t];
        __syncthreads();
        for (int off = 1; off < 256; off <<= 1) {
            int v2 = 0;
            if (t < 256 && t + off < 256) v2 = sfx[t + off];
            __syncthreads();
            if (t < 256) sfx[t] += v2;
            __syncthreads();
        }
        if (t < 256) {
            int excl = (t < 255) ? sfx[t + 1] : 0;
            if (excl < remk && remk <= excl + hist[t]) {
                s_bin = t;
                s_remk = remk - excl;
            }
        }
        __syncthreads();
        if (t == 0) s_pref = (s_pref << 8) | (unsigned)s_bin;
        __syncthreads();
    }
    unsigned Tkey = s_pref;

    for (int i = t; i < NPG; i += 1024) {
        int v = base + i;
        float keep = (key[i] >= Tkey) ? 1.f : 0.f;
        g_nmask[v] = keep;
        g_rows[v] = keep * tanhf(sc[i]);
        if (keep == 0.f) g_sr[v] = 0.f;
        sc[i] = keep;
    }
    __syncthreads();

    int k4 = t * 4;
    int cnt = 0;
#pragma unroll
    for (int j = 0; j < 4; j++) cnt += (sc[k4 + j] > 0.f) ? 1 : 0;
    int lane_ = t & 31, w_ = t >> 5;
    int x = cnt;
#pragma unroll
    for (int o = 1; o < 32; o <<= 1) {
        int y = __shfl_up_sync(0xffffffff, x, o);
        if (lane_ >= o) x += y;
    }
    if (lane_ == 31) wsum[w_] = x;
    __syncthreads();
    if (w_ == 0) {
        int y = wsum[lane_];
#pragma unroll
        for (int o = 1; o < 32; o <<= 1) {
            int z = __shfl_up_sync(0xffffffff, y, o);
            if (lane_ >= o) y += z;
        }
        wsum[lane_] = y;
    }
    __syncthreads();
    int pos = x - cnt + (w_ ? wsum[w_ - 1] : 0);
#pragma unroll
    for (int j = 0; j < 4; j++) {
        if (sc[k4 + j] > 0.f) { ridx[gph * kkeep + pos] = base + k4 + j; pos++; }
    }
}

// ---------------- readout ----------------------------------------------------
__global__ void k_pool1(const int* __restrict__ ridx3) {
    int g = blockIdx.x >> 4, ch = blockIdx.x & 15, c = threadIdx.x;
    const int* rp = ridx3 + g * K2 + ch * 64;
    float sum = 0.f, mx = -3.4e38f;
    for (int n = 0; n < 64; n++) {
        int node = rp[n];
        float h = g_h[(size_t)node * HID + c];
        sum += h;
        mx = fmaxf(mx, h);
    }
    g_pp_sum[(size_t)blockIdx.x * HID + c] = sum;
    g_pp_max[(size_t)blockIdx.x * HID + c] = mx;
}

__global__ void __launch_bounds__(512)
k_head(const float* __restrict__ fc1w, const float* __restrict__ fc1b,
       const float* __restrict__ fc2w, const float* __restrict__ fc2b,
       float* __restrict__ out) {
    __shared__ float gp[2 * HID];
    __shared__ float f1[HID];
    int g = blockIdx.x, c = threadIdx.x;

    float sum = 0.f, mx = -3.4e38f;
    for (int j = 0; j < 16; j++) {
        sum += g_pp_sum[(size_t)(g * 16 + j) * HID + c];
        mx = fmaxf(mx, g_pp_max[(size_t)(g * 16 + j) * HID + c]);
    }
    gp[c] = sum / (float)K2;
    gp[HID + c] = mx;
    __syncthreads();

    float s = fc1b[c];
    for (int k = 0; k < 2 * HID; k++) s = fmaf(gp[k], fc1w[k * HID + c], s);
    f1[c] = lrelu(s);
    __syncthreads();

    if (c < NCLS) {
        float o = fc2b[c];
        for (int k = 0; k < HID; k++) o = fmaf(f1[k], fc2w[k * NCLS + c], o);
        out[g * NCLS + c] = o;
    }
}

// ---------------- launch -----------------------------------------------------
extern "C" void kernel_launch(void* const* d_in, const int* in_sizes, int n_in,
                              void* d_out, int out_size) {
    const float* x     = (const float*)d_in[0];
    const int*   esrc  = (const int*)d_in[1];
    const int*   edst  = (const int*)d_in[2];
    const float* W1    = (const float*)d_in[3];
    const float* b1    = (const float*)d_in[4];
    const float* p1wr  = (const float*)d_in[5];
    const float* p1br  = (const float*)d_in[6];
    const float* p1wo  = (const float*)d_in[7];
    const float* W2    = (const float*)d_in[8];
    const float* b2    = (const float*)d_in[9];
    const float* p2wr  = (const float*)d_in[10];
    const float* p2br  = (const float*)d_in[11];
    const float* p2wo  = (const float*)d_in[12];
    const float* W3    = (const float*)d_in[13];
    const float* b3    = (const float*)d_in[14];
    const float* fc1w  = (const float*)d_in[15];
    const float* fc1b  = (const float*)d_in[16];
    const float* fc2w  = (const float*)d_in[17];
    const float* fc2b  = (const float*)d_in[18];
    float* out = (float*)d_out;

    float*  dT;     cudaGetSymbolAddress((void**)&dT, g_t);
    float*  dH;     cudaGetSymbolAddress((void**)&dH, g_h);
    float*  dRS;    cudaGetSymbolAddress((void**)&dRS, g_rows);
    __half* dW1hi;  cudaGetSymbolAddress((void**)&dW1hi, g_w1t_hi);
    __half* dW1lo;  cudaGetSymbolAddress((void**)&dW1lo, g_w1t_lo);
    __half* dW2hi;  cudaGetSymbolAddress((void**)&dW2hi, g_w2t_hi);
    __half* dW2lo;  cudaGetSymbolAddress((void**)&dW2lo, g_w2t_lo);
    __half* dW3hi;  cudaGetSymbolAddress((void**)&dW3hi, g_w3t_hi);
    __half* dW3lo;  cudaGetSymbolAddress((void**)&dW3lo, g_w3t_lo);
    int*    dIota;  cudaGetSymbolAddress((void**)&dIota, g_iota);
    int*    dR2;    cudaGetSymbolAddress((void**)&dR2, g_ridx2);
    int*    dR3;    cudaGetSymbolAddress((void**)&dR3, g_ridx3);

    static cudaStream_t s_side = 0;
    static cudaEvent_t  e_fork = 0, e_join = 0;
    static int cfg_done = 0;
    if (!cfg_done) {   // first (non-captured) call only; host-side config
        cudaFuncSetAttribute(mma_gemm, cudaFuncAttributeMaxDynamicSharedMemorySize, SM_BYTES);
        cudaStreamCreateWithFlags(&s_side, cudaStreamNonBlocking);
        cudaEventCreateWithFlags(&e_fork, cudaEventDisableTiming);
        cudaEventCreateWithFlags(&e_join, cudaEventDisableTiming);
        cfg_done = 1;
    }

    // ---- main: init + W1 split; fork side stream for graph preprocessing ----
    k_init<<<NN / 256, 256>>>();
    cudaEventRecord(e_fork, 0);
    cudaStreamWaitEvent(s_side, e_fork, 0);

    // side: CSR build + W2/W3 splits (independent of GEMM1)
    k_count<<<EE / 256, 256, 0, s_side>>>(edst);
    k_scan<<<1, 1024, 0, s_side>>>();
    k_scatter<<<EE / 256, 256, 0, s_side>>>(esrc, edst);
    k_wsplitT2<<<dim3(HID / 32, HID / 32, 2), dim3(32, 8), 0, s_side>>>(
        W2, dW2hi, dW2lo, W3, dW3hi, dW3lo);
    cudaEventRecord(e_join, s_side);

    // main: W1 split + layer-1 GEMM (overlaps side stream)
    k_wsplitT<<<dim3(HID / 32, INC / 32), dim3(32, 8)>>>(W1, dW1hi, dW1lo, INC, HID);
    mma_gemm<<<dim3(HID / 128, NN / 128), 512, SM_BYTES>>>(x, dW1hi, dW1lo, dRS, dIota, dT, INC);

    // join: CSR + dinv needed from here on
    cudaStreamWaitEvent(0, e_join, 0);

    // ---- layer 1 epilogue + pool 1 ----
    k_agg<<<NN, 128>>>(b1, p1wr, p1wo, 1, 1, dIota);
    k_score<<<NN / 256, 256>>>(p1br);
    k_topk<<<BB, 1024>>>(K1, dR2);
    k_deg<<<NN / 256, 256>>>();

    // ---- layer 2 ----
    mma_gemm<<<dim3(HID / 128, NACT2 / 128), 512, SM_BYTES>>>(dH, dW2hi, dW2lo, dRS, dR2, dT, HID);
    k_agg<<<NACT2, 128>>>(b2, p2wr, p2wo, 1, 0, dR2);
    k_score<<<NN / 256, 256>>>(p2br);
    k_topk<<<BB, 1024>>>(K2, dR3);
    k_deg<<<NN / 256, 256>>>();

    // ---- layer 3 ----
    mma_gemm<<<dim3(HID / 128, NACT3 / 128), 512, SM_BYTES>>>(dH, dW3hi, dW3lo, dRS, dR3, dT, HID);
    k_agg<<<NACT3, 128>>>(b3, (const float*)0, (const float*)0, 0, 0, dR3);

    // ---- readout ----
    k_pool1<<<BB * 16, HID>>>(dR3);
    k_head<<<BB, HID>>>(fc1w, fc1b, fc2w, fc2b, out);
}

// round 15
// speedup vs baseline: 1.5804x; 1.0642x over previous
#include <cuda_runtime.h>
#include <cuda_fp16.h>
#include <math.h>
#include <stdint.h>

#define BB    8
#define NPG   4096
#define NN    32768
#define EE    262144
#define INC   1024
#define HID   512
#define NCLS  4
#define K1    2048
#define K2    1024
#define NACT2 (BB*K1)
#define NACT3 (BB*K2)
#define HGRAPH 4                 /* graphs per half */
#define HNODE  (HGRAPH*NPG)      /* 16384 nodes per half */

// ---------------- scratch (device globals; no allocations allowed) ----------
__device__ float g_t[NN * HID];
__device__ float g_h[NN * HID];
__device__ float g_dinv[NN];
__device__ float g_nmask[NN];
__device__ float g_rows[NN];
__device__ float g_sr[NN];
__device__ float g_so[NN];
__device__ float g_score[NN];
__device__ int   g_cnt[NN];
__device__ int   g_off[NN + 1];
__device__ int   g_cur[NN];
__device__ int   g_csr[EE];
__device__ __half g_w1t_hi[HID * INC];
__device__ __half g_w1t_lo[HID * INC];
__device__ __half g_w2t_hi[HID * HID];
__device__ __half g_w2t_lo[HID * HID];
__device__ __half g_w3t_hi[HID * HID];
__device__ __half g_w3t_lo[HID * HID];
__device__ int   g_iota[NN];
__device__ int   g_ridx2[NACT2 + 64];
__device__ int   g_ridx3[NACT3 + 64];
__device__ float g_pp_sum[BB * 16 * HID];
__device__ float g_pp_max[BB * 16 * HID];

__device__ __forceinline__ float lrelu(float x) { return x > 0.f ? x : 0.01f * x; }

// ---------------- fp16 m16n8k16 mma (base-target PTX, sm_80+) ---------------
__device__ __forceinline__ void mma16(float* c, uint4 a, uint2 b) {
    asm volatile(
        "mma.sync.aligned.m16n8k16.row.col.f32.f16.f16.f32 "
        "{%0,%1,%2,%3}, {%4,%5,%6,%7}, {%8,%9}, {%0,%1,%2,%3};"
        : "+f"(c[0]), "+f"(c[1]), "+f"(c[2]), "+f"(c[3])
        : "r"(a.x), "r"(a.y), "r"(a.z), "r"(a.w), "r"(b.x), "r"(b.y));
}

// ======= fp16x3 HMMA GEMM: block 128x128, BK=32, 512 thr (16 warps 4x4) =====
#define AREG_B   576
#define AMAT_B   (16 * AREG_B)
#define BREG_B   296
#define BMAT_B   (32 * BREG_B)
#define STG_B    (2*AMAT_B + 2*BMAT_B)
#define SM_BYTES (1024 + 2 * STG_B)         /* 75776 */

__global__ void __launch_bounds__(512, 1)
mma_gemm(const float* __restrict__ A, const __half* __restrict__ Bhi,
         const __half* __restrict__ Blo, const float* __restrict__ rs,
         const int* __restrict__ ridx, float* __restrict__ C, int K)
{
    extern __shared__ char smc[];
    int*   ridx_s = (int*)smc;
    float* rs_s   = (float*)(smc + 512);
    char*  stg    = smc + 1024;

    int tid = threadIdx.x;
    int lane = tid & 31, wid = tid >> 5;
    int g = lane >> 2, tg = lane & 3;
    int wm = wid & 3, wn = wid >> 2;
    int nb = blockIdx.x, mb = blockIdx.y;

    if (tid < 128) {
        int r = ridx[mb * 128 + tid];
        ridx_s[tid] = r;
        rs_s[tid] = rs[r];
    }
    __syncthreads();

    float acc[2][4][4];
#pragma unroll
    for (int a = 0; a < 2; a++)
#pragma unroll
        for (int b = 0; b < 4; b++)
#pragma unroll
            for (int q = 0; q < 4; q++) acc[a][b][q] = 0.f;

    int jm[2], jc[2];
    const float* pa[2];
    const __half *pbh[2], *pbl[2];
#pragma unroll
    for (int i = 0; i < 2; i++) {
        int j = tid + 512 * i;
        jm[i] = j >> 3; jc[i] = (j & 7) * 4;
        pa[i]  = A   + (size_t)ridx_s[jm[i]] * K + jc[i];
        pbh[i] = Bhi + (size_t)(nb * 128 + jm[i]) * K + jc[i];
        pbl[i] = Blo + (size_t)(nb * 128 + jm[i]) * K + jc[i];
    }

    float4 sa[2];
    uint2  sbh[2], sbl[2];

    auto do_ldg = [&]() {
#pragma unroll
        for (int i = 0; i < 2; i++) {
            sa[i]  = *(const float4*)pa[i];  pa[i]  += 32;
            sbh[i] = *(const uint2*)pbh[i]; pbh[i] += 32;
            sbl[i] = *(const uint2*)pbl[i]; pbl[i] += 32;
        }
    };

    auto do_sts = [&](int s) {
        char* base = stg + s * STG_B;
#pragma unroll
        for (int i = 0; i < 2; i++) {
            int m = jm[i], c4 = jc[i];
            int k16 = c4 >> 4, kk = c4 & 15;
            int tg0 = (kk >> 1) & 3;
            int slot = ((kk >= 8) ? 2 : 0) + ((m & 15) >> 3);
            int aoff = ((m >> 4) * 2 + k16) * AREG_B + ((m & 7) * 4 + tg0) * 16 + slot * 4;
            __half hx = __float2half_rn(sa[i].x), hy = __float2half_rn(sa[i].y);
            __half hz = __float2half_rn(sa[i].z), hw = __float2half_rn(sa[i].w);
            *(__half2*)(base + aoff)      = __halves2half2(hx, hy);
            *(__half2*)(base + aoff + 16) = __halves2half2(hz, hw);
            __half lx = __float2half_rn(sa[i].x - __half2float(hx));
            __half ly = __float2half_rn(sa[i].y - __half2float(hy));
            __half lz = __float2half_rn(sa[i].z - __half2float(hz));
            __half lw = __float2half_rn(sa[i].w - __half2float(hw));
            *(__half2*)(base + AMAT_B + aoff)      = __halves2half2(lx, ly);
            *(__half2*)(base + AMAT_B + aoff + 16) = __halves2half2(lz, lw);
            int boff = ((m >> 3) * 2 + k16) * BREG_B + ((m & 7) * 4 + tg0) * 8 + ((kk >= 8) ? 4 : 0);
            char* Bh = base + 2 * AMAT_B;
            char* Bl = Bh + BMAT_B;
            *(uint32_t*)(Bh + boff)     = sbh[i].x;
            *(uint32_t*)(Bh + boff + 8) = sbh[i].y;
            *(uint32_t*)(Bl + boff)     = sbl[i].x;
            *(uint32_t*)(Bl + boff + 8) = sbl[i].y;
        }
    };

    auto do_comp = [&](int s) {
        const char* base = stg + s * STG_B;
#pragma unroll
        for (int k16 = 0; k16 < 2; k16++) {
            uint4 ah[2], al[2];
#pragma unroll
            for (int tm = 0; tm < 2; tm++) {
                int m16 = wm * 2 + tm;
                const char* pA = base + (m16 * 2 + k16) * AREG_B + lane * 16;
                ah[tm] = *(const uint4*)pA;
                al[tm] = *(const uint4*)(pA + AMAT_B);
            }
#pragma unroll
            for (int tn = 0; tn < 4; tn++) {
                int n8 = wn * 4 + tn;
                const char* pB = base + 2 * AMAT_B + (n8 * 2 + k16) * BREG_B + lane * 8;
                uint2 bh = *(const uint2*)pB;
                uint2 bl = *(const uint2*)(pB + BMAT_B);
#pragma unroll
                for (int tm = 0; tm < 2; tm++) {
                    mma16(acc[tm][tn], ah[tm], bh);
                    mma16(acc[tm][tn], al[tm], bh);
                    mma16(acc[tm][tn], ah[tm], bl);
                }
            }
        }
    };

    const int NIT = K >> 5;
    do_ldg();
    do_sts(0);
    __syncthreads();
    for (int it = 0; it < NIT; it++) {
        if (it + 1 < NIT) do_ldg();
        do_comp(it & 1);
        if (it + 1 < NIT) do_sts((it + 1) & 1);
        __syncthreads();
    }

#pragma unroll
    for (int tm = 0; tm < 2; tm++) {
        int r0 = wm * 32 + tm * 16 + g;
        float s0 = rs_s[r0], s1 = rs_s[r0 + 8];
        size_t o0 = (size_t)ridx_s[r0] * HID;
        size_t o1 = (size_t)ridx_s[r0 + 8] * HID;
#pragma unroll
        for (int tn = 0; tn < 4; tn++) {
            int n0 = nb * 128 + wn * 32 + tn * 8 + 2 * tg;
            *(float2*)(C + o0 + n0) = make_float2(acc[tm][tn][0] * s0, acc[tm][tn][1] * s0);
            *(float2*)(C + o1 + n0) = make_float2(acc[tm][tn][2] * s1, acc[tm][tn][3] * s1);
        }
    }
}

// ---- coalesced transpose + fp16-split ---------------------------------------
__global__ void k_wsplitT(const float* __restrict__ W, __half* __restrict__ hi,
                          __half* __restrict__ lo, int K, int N) {
    __shared__ float tile[32][33];
    int kb = blockIdx.y * 32, nb = blockIdx.x * 32;
    int tx = threadIdx.x, ty = threadIdx.y;
#pragma unroll
    for (int r = ty; r < 32; r += 8)
        tile[r][tx] = W[(size_t)(kb + r) * N + nb + tx];
    __syncthreads();
#pragma unroll
    for (int r = ty; r < 32; r += 8) {
        float v = tile[tx][r];
        __half h = __float2half_rn(v);
        size_t o = (size_t)(nb + r) * K + kb + tx;
        hi[o] = h;
        lo[o] = __float2half_rn(v - __half2float(h));
    }
}

// ---- W2+W3 in one launch (blockIdx.z selects) -------------------------------
__global__ void k_wsplitT2(const float* __restrict__ Wa, __half* __restrict__ hia,
                           __half* __restrict__ loa, const float* __restrict__ Wb,
                           __half* __restrict__ hib, __half* __restrict__ lob) {
    __shared__ float tile[32][33];
    const float* W = blockIdx.z ? Wb : Wa;
    __half* hi = blockIdx.z ? hib : hia;
    __half* lo = blockIdx.z ? lob : loa;
    int kb = blockIdx.y * 32, nb = blockIdx.x * 32;
    int tx = threadIdx.x, ty = threadIdx.y;
#pragma unroll
    for (int r = ty; r < 32; r += 8)
        tile[r][tx] = W[(size_t)(kb + r) * HID + nb + tx];
    __syncthreads();
#pragma unroll
    for (int r = ty; r < 32; r += 8) {
        float v = tile[tx][r];
        __half h = __float2half_rn(v);
        size_t o = (size_t)(nb + r) * HID + kb + tx;
        hi[o] = h;
        lo[o] = __float2half_rn(v - __half2float(h));
    }
}

// ---------------- graph preprocessing ---------------------------------------
__global__ void k_init() {
    int i = blockIdx.x * blockDim.x + threadIdx.x;
    if (i < NN) { g_cnt[i] = 0; g_nmask[i] = 1.f; g_rows[i] = 1.f; g_iota[i] = i; }
}

__global__ void k_count(const int* __restrict__ dst) {
    int e = blockIdx.x * blockDim.x + threadIdx.x;
    if (e < EE) atomicAdd(&g_cnt[dst[e]], 1);
}

__global__ void k_scan() {   // CSR offsets + layer-1 dinv
    __shared__ int part[1024];
    int t = threadIdx.x;
    int base = t * 32;
    int s = 0;
#pragma unroll
    for (int i = 0; i < 32; i++) s += g_cnt[base + i];
    part[t] = s;
    __syncthreads();
    for (int off = 1; off < 1024; off <<= 1) {
        int v = (t >= off) ? part[t - off] : 0;
        __syncthreads();
        part[t] += v;
        __syncthreads();
    }
    int run = (t == 0) ? 0 : part[t - 1];
#pragma unroll
    for (int i = 0; i < 32; i++) {
        int c = g_cnt[base + i];
        g_off[base + i] = run;
        g_cur[base + i] = run;
        g_dinv[base + i] = rsqrtf((float)c + 1.f);
        run += c;
    }
    if (t == 1023) g_off[NN] = run;
}

__global__ void k_scatter(const int* __restrict__ src, const int* __restrict__ dst) {
    int e = blockIdx.x * blockDim.x + threadIdx.x;
    if (e < EE) {
        int p = atomicAdd(&g_cur[dst[e]], 1);
        g_csr[p] = src[e];
    }
}

// ---- agg + lrelu + fused pool dots; optional active-neighbor compaction ----
__global__ void k_agg(const float* __restrict__ bias, const float* __restrict__ wr,
                      const float* __restrict__ wo, int dopool, int allact,
                      const int* __restrict__ map) {
    __shared__ float s_ds[128];
    __shared__ int   s_src[128];
    __shared__ float s2[8];
    __shared__ int   s_cnt;
    int v = map[blockIdx.x];
    int c = threadIdx.x;
    int lane = c & 31;
    float dv = g_dinv[v];
    int e0 = g_off[v], deg = g_off[v + 1] - e0;

    float4 a = make_float4(0.f, 0.f, 0.f, 0.f);
    for (int base = 0; base < deg; base += 128) {
        int n = deg - base; if (n > 128) n = 128;
        int nact;
        if (allact) {
            if (c < n) {
                int s = g_csr[e0 + base + c];
                s_src[c] = s;
                s_ds[c] = g_dinv[s];
            }
            nact = n;
            __syncthreads();
        } else {
            if (c == 0) s_cnt = 0;
            __syncthreads();
            bool inb = c < n;
            int s = 0; float ds = 0.f;
            if (inb) { s = g_csr[e0 + base + c]; ds = g_dinv[s]; }
            bool act = inb && (ds != 0.f);
            unsigned m = __ballot_sync(0xffffffffu, act);
            int rank = __popc(m & ((1u << lane) - 1));
            int wbase = 0;
            if (lane == 0) wbase = atomicAdd(&s_cnt, __popc(m));
            wbase = __shfl_sync(0xffffffffu, wbase, 0);
            if (act) { s_src[wbase + rank] = s; s_ds[wbase + rank] = ds; }
            __syncthreads();
            nact = s_cnt;
        }
        int i = 0;
        for (; i + 2 <= nact; i += 2) {
            float ds0 = s_ds[i],   ds1 = s_ds[i + 1];
            float4 t0 = *((const float4*)(g_t + (size_t)s_src[i]     * HID) + c);
            float4 t1 = *((const float4*)(g_t + (size_t)s_src[i + 1] * HID) + c);
            a.x += ds0 * t0.x + ds1 * t1.x;
            a.y += ds0 * t0.y + ds1 * t1.y;
            a.z += ds0 * t0.z + ds1 * t1.z;
            a.w += ds0 * t0.w + ds1 * t1.w;
        }
        if (i < nact) {
            float ds0 = s_ds[i];
            float4 t0 = *((const float4*)(g_t + (size_t)s_src[i] * HID) + c);
            a.x += ds0 * t0.x; a.y += ds0 * t0.y;
            a.z += ds0 * t0.z; a.w += ds0 * t0.w;
        }
        __syncthreads();
    }

    float4 tv = *((const float4*)(g_t + (size_t)v * HID) + c);
    float4 bi = *((const float4*)bias + c);
    float dv2 = dv * dv;
    float4 h;
    h.x = lrelu(dv * a.x + dv2 * tv.x + bi.x);
    h.y = lrelu(dv * a.y + dv2 * tv.y + bi.y);
    h.z = lrelu(dv * a.z + dv2 * tv.z + bi.z);
    h.w = lrelu(dv * a.w + dv2 * tv.w + bi.w);
    *((float4*)(g_h + (size_t)v * HID) + c) = h;

    if (dopool) {
        float4 r4 = *((const float4*)wr + c);
        float4 o4 = *((const float4*)wo + c);
        float pr = h.x * r4.x + h.y * r4.y + h.z * r4.z + h.w * r4.w;
        float po = h.x * o4.x + h.y * o4.y + h.z * o4.z + h.w * o4.w;
#pragma unroll
        for (int o = 16; o > 0; o >>= 1) {
            pr += __shfl_down_sync(0xffffffff, pr, o);
            po += __shfl_down_sync(0xffffffff, po, o);
        }
        int wd = c >> 5;
        if (lane == 0) { s2[wd * 2] = pr; s2[wd * 2 + 1] = po; }
        __syncthreads();
        if (c == 0) {
            g_sr[v] = s2[0] + s2[2] + s2[4] + s2[6];
            g_so[v] = s2[1] + s2[3] + s2[5] + s2[7];
        }
    }
}

// ---- half-batch score (nodebase = half * HNODE) -----------------------------
__global__ void k_score(const float* __restrict__ br, int nodebase) {
    int v = nodebase + blockIdx.x * blockDim.x + threadIdx.x;
    if (g_nmask[v] <= 0.f) { g_score[v] = -1e30f; return; }
    float s = br[0] + g_so[v];
    int e0 = g_off[v], e1 = g_off[v + 1];
    for (int i = e0; i < e1; i++) s += g_sr[g_csr[i]];
    g_score[v] = s;
}

// ---- half-batch next-layer deg ----------------------------------------------
__global__ void k_deg(int nodebase) {
    int v = nodebase + blockIdx.x * blockDim.x + threadIdx.x;
    if (g_nmask[v] <= 0.f) { g_dinv[v] = 0.f; return; }
    float s = 1.f;
    int e0 = g_off[v], e1 = g_off[v + 1];
    for (int i = e0; i < e1; i++) s += g_nmask[g_csr[i]];
    g_dinv[v] = rsqrtf(s);
}

// ---- per-graph radix-select topk + mask/rows/sr-zero + compact (goff base) -
__global__ void __launch_bounds__(1024)
k_topk(int goff, int kkeep, int* __restrict__ ridx) {
    __shared__ float    sc[NPG];
    __shared__ unsigned key[NPG];
    __shared__ int hist[256];
    __shared__ int sfx[256];
    __shared__ int wsum[32];
    __shared__ int s_bin, s_remk;
    __shared__ unsigned s_pref;
    int gph = goff + blockIdx.x, t = threadIdx.x;
    int base = gph * NPG;

    for (int i = t; i < NPG; i += 1024) {
        float s = g_score[base + i];
        sc[i] = s;
        unsigned u = __float_as_uint(s);
        key[i] = (u & 0x80000000u) ? ~u : (u | 0x80000000u);
    }
    if (t == 0) { s_remk = kkeep; s_pref = 0u; }
    __syncthreads();

    for (int shift = 24; shift >= 0; shift -= 8) {
        if (t < 256) hist[t] = 0;
        __syncthreads();
        unsigned pref = s_pref;
        int remk = s_remk;
        for (int i = t; i < NPG; i += 1024) {
            unsigned u = key[i];
            bool ok = (shift == 24) || ((u >> (shift + 8)) == pref);
            if (ok) atomicAdd(&hist[(u >> shift) & 255], 1);
        }
        __syncthreads();
        if (t < 256) sfx[t] = hist[t];
        __syncthreads();
        for (int off = 1; off < 256; off <<= 1) {
            int v2 = 0;
            if (t < 256 && t + off < 256) v2 = sfx[t + off];
            __syncthreads();
            if (t < 256) sfx[t] += v2;
            __syncthreads();
        }
        if (t < 256) {
            int excl = (t < 255) ? sfx[t + 1] : 0;
            if (excl < remk && remk <= excl + hist[t]) {
                s_bin = t;
                s_remk = remk - excl;
            }
        }
        __syncthreads();
        if (t == 0) s_pref = (s_pref << 8) | (unsigned)s_bin;
        __syncthreads();
    }
    unsigned Tkey = s_pref;

    for (int i = t; i < NPG; i += 1024) {
        int v = base + i;
        float keep = (key[i] >= Tkey) ? 1.f : 0.f;
        g_nmask[v] = keep;
        g_rows[v] = keep * tanhf(sc[i]);
        if (keep == 0.f) g_sr[v] = 0.f;
        sc[i] = keep;
    }
    __syncthreads();

    int k4 = t * 4;
    int cnt = 0;
#pragma unroll
    for (int j = 0; j < 4; j++) cnt += (sc[k4 + j] > 0.f) ? 1 : 0;
    int lane_ = t & 31, w_ = t >> 5;
    int x = cnt;
#pragma unroll
    for (int o = 1; o < 32; o <<= 1) {
        int y = __shfl_up_sync(0xffffffff, x, o);
        if (lane_ >= o) x += y;
    }
    if (lane_ == 31) wsum[w_] = x;
    __syncthreads();
    if (w_ == 0) {
        int y = wsum[lane_];
#pragma unroll
        for (int o = 1; o < 32; o <<= 1) {
            int z = __shfl_up_sync(0xffffffff, y, o);
            if (lane_ >= o) y += z;
        }
        wsum[lane_] = y;
    }
    __syncthreads();
    int pos = x - cnt + (w_ ? wsum[w_ - 1] : 0);
#pragma unroll
    for (int j = 0; j < 4; j++) {
        if (sc[k4 + j] > 0.f) { ridx[gph * kkeep + pos] = base + k4 + j; pos++; }
    }
}

// ---------------- readout (half batch; goff = first graph) -------------------
__global__ void k_pool1(int goff, const int* __restrict__ ridx3) {  // grid 4*16
    int g = goff + (blockIdx.x >> 4), ch = blockIdx.x & 15, c = threadIdx.x;
    const int* rp = ridx3 + g * K2 + ch * 64;
    float sum = 0.f, mx = -3.4e38f;
    for (int n = 0; n < 64; n++) {
        int node = rp[n];
        float h = g_h[(size_t)node * HID + c];
        sum += h;
        mx = fmaxf(mx, h);
    }
    g_pp_sum[(size_t)(g * 16 + ch) * HID + c] = sum;
    g_pp_max[(size_t)(g * 16 + ch) * HID + c] = mx;
}

__global__ void __launch_bounds__(512)
k_head(int goff, const float* __restrict__ fc1w, const float* __restrict__ fc1b,
       const float* __restrict__ fc2w, const float* __restrict__ fc2b,
       float* __restrict__ out) {
    __shared__ float gp[2 * HID];
    __shared__ float f1[HID];
    int g = goff + blockIdx.x, c = threadIdx.x;

    float sum = 0.f, mx = -3.4e38f;
    for (int j = 0; j < 16; j++) {
        sum += g_pp_sum[(size_t)(g * 16 + j) * HID + c];
        mx = fmaxf(mx, g_pp_max[(size_t)(g * 16 + j) * HID + c]);
    }
    gp[c] = sum / (float)K2;
    gp[HID + c] = mx;
    __syncthreads();

    float s = fc1b[c];
    for (int k = 0; k < 2 * HID; k++) s = fmaf(gp[k], fc1w[k * HID + c], s);
    f1[c] = lrelu(s);
    __syncthreads();

    if (c < NCLS) {
        float o = fc2b[c];
        for (int k = 0; k < HID; k++) o = fmaf(f1[k], fc2w[k * NCLS + c], o);
        out[g * NCLS + c] = o;
    }
}

// ---------------- launch -----------------------------------------------------
extern "C" void kernel_launch(void* const* d_in, const int* in_sizes, int n_in,
                              void* d_out, int out_size) {
    const float* x     = (const float*)d_in[0];
    const int*   esrc  = (const int*)d_in[1];
    const int*   edst  = (const int*)d_in[2];
    const float* W1    = (const float*)d_in[3];
    const float* b1    = (const float*)d_in[4];
    const float* p1wr  = (const float*)d_in[5];
    const float* p1br  = (const float*)d_in[6];
    const float* p1wo  = (const float*)d_in[7];
    const float* W2    = (const float*)d_in[8];
    const float* b2    = (const float*)d_in[9];
    const float* p2wr  = (const float*)d_in[10];
    const float* p2br  = (const float*)d_in[11];
    const float* p2wo  = (const float*)d_in[12];
    const float* W3    = (const float*)d_in[13];
    const float* b3    = (const float*)d_in[14];
    const float* fc1w  = (const float*)d_in[15];
    const float* fc1b  = (const float*)d_in[16];
    const float* fc2w  = (const float*)d_in[17];
    const float* fc2b  = (const float*)d_in[18];
    float* out = (float*)d_out;

    float*  dT;     cudaGetSymbolAddress((void**)&dT, g_t);
    float*  dH;     cudaGetSymbolAddress((void**)&dH, g_h);
    float*  dRS;    cudaGetSymbolAddress((void**)&dRS, g_rows);
    __half* dW1hi;  cudaGetSymbolAddress((void**)&dW1hi, g_w1t_hi);
    __half* dW1lo;  cudaGetSymbolAddress((void**)&dW1lo, g_w1t_lo);
    __half* dW2hi;  cudaGetSymbolAddress((void**)&dW2hi, g_w2t_hi);
    __half* dW2lo;  cudaGetSymbolAddress((void**)&dW2lo, g_w2t_lo);
    __half* dW3hi;  cudaGetSymbolAddress((void**)&dW3hi, g_w3t_hi);
    __half* dW3lo;  cudaGetSymbolAddress((void**)&dW3lo, g_w3t_lo);
    int*    dIota;  cudaGetSymbolAddress((void**)&dIota, g_iota);
    int*    dR2;    cudaGetSymbolAddress((void**)&dR2, g_ridx2);
    int*    dR3;    cudaGetSymbolAddress((void**)&dR3, g_ridx3);

    static cudaStream_t s_side = 0;
    static cudaEvent_t  e_fork = 0, e_w1 = 0, e_csr = 0, e_w23 = 0, e_join = 0;
    static int cfg_done = 0;
    if (!cfg_done) {   // first (non-captured) call only; host-side config
        cudaFuncSetAttribute(mma_gemm, cudaFuncAttributeMaxDynamicSharedMemorySize, SM_BYTES);
        cudaStreamCreateWithFlags(&s_side, cudaStreamNonBlocking);
        cudaEventCreateWithFlags(&e_fork, cudaEventDisableTiming);
        cudaEventCreateWithFlags(&e_w1,   cudaEventDisableTiming);
        cudaEventCreateWithFlags(&e_csr,  cudaEventDisableTiming);
        cudaEventCreateWithFlags(&e_w23,  cudaEventDisableTiming);
        cudaEventCreateWithFlags(&e_join, cudaEventDisableTiming);
        cfg_done = 1;
    }

    // half-batch chain (after this half's GEMM1; CSR + W2/W3 must be ready)
    auto chain = [&](cudaStream_t sg, int half) {
        int goff = half * HGRAPH;
        int nb = half * HNODE;
        k_agg<<<HNODE, 128, 0, sg>>>(b1, p1wr, p1wo, 1, 1, dIota + nb);
        k_score<<<HNODE / 256, 256, 0, sg>>>(p1br, nb);
        k_topk<<<HGRAPH, 1024, 0, sg>>>(goff, K1, dR2);
        k_deg<<<HNODE / 256, 256, 0, sg>>>(nb);
        mma_gemm<<<dim3(HID / 128, (HGRAPH * K1) / 128), 512, SM_BYTES, sg>>>(
            dH, dW2hi, dW2lo, dRS, dR2 + goff * K1, dT, HID);
        k_agg<<<HGRAPH * K1, 128, 0, sg>>>(b2, p2wr, p2wo, 1, 0, dR2 + goff * K1);
        k_score<<<HNODE / 256, 256, 0, sg>>>(p2br, nb);
        k_topk<<<HGRAPH, 1024, 0, sg>>>(goff, K2, dR3);
        k_deg<<<HNODE / 256, 256, 0, sg>>>(nb);
        mma_gemm<<<dim3(HID / 128, (HGRAPH * K2) / 128), 512, SM_BYTES, sg>>>(
            dH, dW3hi, dW3lo, dRS, dR3 + goff * K2, dT, HID);
        k_agg<<<HGRAPH * K2, 128, 0, sg>>>(b3, (const float*)0, (const float*)0, 0, 0,
                                           dR3 + goff * K2);
        k_pool1<<<HGRAPH * 16, HID, 0, sg>>>(goff, dR3);
        k_head<<<HGRAPH, HID, 0, sg>>>(goff, fc1w, fc1b, fc2w, fc2b, out);
    };

    // ---- shared preprocessing ----
    k_init<<<NN / 256, 256>>>();
    cudaEventRecord(e_fork, 0);
    cudaStreamWaitEvent(s_side, e_fork, 0);

    // side: CSR build, then W2/W3 splits
    k_count<<<EE / 256, 256, 0, s_side>>>(edst);
    k_scan<<<1, 1024, 0, s_side>>>();
    k_scatter<<<EE / 256, 256, 0, s_side>>>(esrc, edst);
    cudaEventRecord(e_csr, s_side);
    k_wsplitT2<<<dim3(HID / 32, HID / 32, 2), dim3(32, 8), 0, s_side>>>(
        W2, dW2hi, dW2lo, W3, dW3hi, dW3lo);
    cudaEventRecord(e_w23, s_side);

    // main: W1 split
    k_wsplitT<<<dim3(HID / 32, INC / 32), dim3(32, 8)>>>(W1, dW1hi, dW1lo, INC, HID);
    cudaEventRecord(e_w1, 0);

    // ---- half A on main: GEMM1 rows 0..HNODE-1, then chain for graphs 0-3 ----
    mma_gemm<<<dim3(HID / 128, HNODE / 128), 512, SM_BYTES>>>(
        x, dW1hi, dW1lo, dRS, dIota, dT, INC);
    cudaStreamWaitEvent(0, e_csr, 0);
    cudaStreamWaitEvent(0, e_w23, 0);
    chain(0, 0);

    // ---- half B on side: GEMM1 rows HNODE.., then chain for graphs 4-7 ----
    cudaStreamWaitEvent(s_side, e_w1, 0);
    mma_gemm<<<dim3(HID / 128, HNODE / 128), 512, SM_BYTES, s_side>>>(
        x, dW1hi, dW1lo, dRS, dIota + HNODE, dT, INC);
    chain(s_side, 1);
    cudaEventRecord(e_join, s_side);

    // join
    cudaStreamWaitEvent(0, e_join, 0);
}

// round 16
// speedup vs baseline: 1.5857x; 1.0033x over previous
#include <cuda_runtime.h>
#include <cuda_fp16.h>
#include <math.h>
#include <stdint.h>

#define BB    8
#define NPG   4096
#define NN    32768
#define EE    262144
#define INC   1024
#define HID   512
#define NCLS  4
#define K1    2048
#define K2    1024
#define NACT2 (BB*K1)
#define NACT3 (BB*K2)
#define HGRAPH 4
#define HNODE  (HGRAPH*NPG)

// ---------------- scratch (device globals; no allocations allowed) ----------
__device__ float g_t[NN * HID];
__device__ float g_h[NN * HID];
__device__ float g_dinv[NN];
__device__ float g_nmask[NN];
__device__ float g_rows[NN];
__device__ float g_sr[NN];
__device__ float g_so[NN];
__device__ float g_score[NN];
__device__ int   g_cnt[NN];
__device__ int   g_off[NN + 1];
__device__ int   g_cur[NN];
__device__ int   g_csr[EE];
__device__ __half g_w1t_hi[HID * INC];
__device__ __half g_w1t_lo[HID * INC];
__device__ __half g_w2t_hi[HID * HID];
__device__ __half g_w2t_lo[HID * HID];
__device__ __half g_w3t_hi[HID * HID];
__device__ __half g_w3t_lo[HID * HID];
__device__ int   g_iota[NN];
__device__ int   g_ridx2[NACT2 + 64];
__device__ int   g_ridx3[NACT3 + 64];
__device__ float g_pp_sum[BB * 16 * HID];
__device__ float g_pp_max[BB * 16 * HID];

__device__ __forceinline__ float lrelu(float x) { return x > 0.f ? x : 0.01f * x; }

// ---------------- fp16 m16n8k16 mma (base-target PTX, sm_80+) ---------------
__device__ __forceinline__ void mma16(float* c, uint4 a, uint2 b) {
    asm volatile(
        "mma.sync.aligned.m16n8k16.row.col.f32.f16.f16.f32 "
        "{%0,%1,%2,%3}, {%4,%5,%6,%7}, {%8,%9}, {%0,%1,%2,%3};"
        : "+f"(c[0]), "+f"(c[1]), "+f"(c[2]), "+f"(c[3])
        : "r"(a.x), "r"(a.y), "r"(a.z), "r"(a.w), "r"(b.x), "r"(b.y));
}

// ======= fp16x3 HMMA GEMM: block 128x128, BK=32, 512 thr (16 warps 4x4) =====
#define AREG_B   576
#define AMAT_B   (16 * AREG_B)
#define BREG_B   296
#define BMAT_B   (32 * BREG_B)
#define STG_B    (2*AMAT_B + 2*BMAT_B)
#define SM_BYTES (1024 + 2 * STG_B)         /* 75776 */

__global__ void __launch_bounds__(512, 1)
mma_gemm(const float* __restrict__ A, const __half* __restrict__ Bhi,
         const __half* __restrict__ Blo, const float* __restrict__ rs,
         const int* __restrict__ ridx, float* __restrict__ C, int K)
{
    extern __shared__ char smc[];
    int*   ridx_s = (int*)smc;
    float* rs_s   = (float*)(smc + 512);
    char*  stg    = smc + 1024;

    int tid = threadIdx.x;
    int lane = tid & 31, wid = tid >> 5;
    int g = lane >> 2, tg = lane & 3;
    int wm = wid & 3, wn = wid >> 2;
    int nb = blockIdx.x, mb = blockIdx.y;

    if (tid < 128) {
        int r = ridx[mb * 128 + tid];
        ridx_s[tid] = r;
        rs_s[tid] = rs[r];
    }
    __syncthreads();

    float acc[2][4][4];
#pragma unroll
    for (int a = 0; a < 2; a++)
#pragma unroll
        for (int b = 0; b < 4; b++)
#pragma unroll
            for (int q = 0; q < 4; q++) acc[a][b][q] = 0.f;

    int jm[2], jc[2];
    const float* pa[2];
    const __half *pbh[2], *pbl[2];
#pragma unroll
    for (int i = 0; i < 2; i++) {
        int j = tid + 512 * i;
        jm[i] = j >> 3; jc[i] = (j & 7) * 4;
        pa[i]  = A   + (size_t)ridx_s[jm[i]] * K + jc[i];
        pbh[i] = Bhi + (size_t)(nb * 128 + jm[i]) * K + jc[i];
        pbl[i] = Blo + (size_t)(nb * 128 + jm[i]) * K + jc[i];
    }

    float4 sa[2];
    uint2  sbh[2], sbl[2];

    auto do_ldg = [&]() {
#pragma unroll
        for (int i = 0; i < 2; i++) {
            sa[i]  = *(const float4*)pa[i];  pa[i]  += 32;
            sbh[i] = *(const uint2*)pbh[i]; pbh[i] += 32;
            sbl[i] = *(const uint2*)pbl[i]; pbl[i] += 32;
        }
    };

    auto do_sts = [&](int s) {
        char* base = stg + s * STG_B;
#pragma unroll
        for (int i = 0; i < 2; i++) {
            int m = jm[i], c4 = jc[i];
            int k16 = c4 >> 4, kk = c4 & 15;
            int tg0 = (kk >> 1) & 3;
            int slot = ((kk >= 8) ? 2 : 0) + ((m & 15) >> 3);
            int aoff = ((m >> 4) * 2 + k16) * AREG_B + ((m & 7) * 4 + tg0) * 16 + slot * 4;
            __half hx = __float2half_rn(sa[i].x), hy = __float2half_rn(sa[i].y);
            __half hz = __float2half_rn(sa[i].z), hw = __float2half_rn(sa[i].w);
            *(__half2*)(base + aoff)      = __halves2half2(hx, hy);
            *(__half2*)(base + aoff + 16) = __halves2half2(hz, hw);
            __half lx = __float2half_rn(sa[i].x - __half2float(hx));
            __half ly = __float2half_rn(sa[i].y - __half2float(hy));
            __half lz = __float2half_rn(sa[i].z - __half2float(hz));
            __half lw = __float2half_rn(sa[i].w - __half2float(hw));
            *(__half2*)(base + AMAT_B + aoff)      = __halves2half2(lx, ly);
            *(__half2*)(base + AMAT_B + aoff + 16) = __halves2half2(lz, lw);
            int boff = ((m >> 3) * 2 + k16) * BREG_B + ((m & 7) * 4 + tg0) * 8 + ((kk >= 8) ? 4 : 0);
            char* Bh = base + 2 * AMAT_B;
            char* Bl = Bh + BMAT_B;
            *(uint32_t*)(Bh + boff)     = sbh[i].x;
            *(uint32_t*)(Bh + boff + 8) = sbh[i].y;
            *(uint32_t*)(Bl + boff)     = sbl[i].x;
            *(uint32_t*)(Bl + boff + 8) = sbl[i].y;
        }
    };

    auto do_comp = [&](int s) {
        const char* base = stg + s * STG_B;
#pragma unroll
        for (int k16 = 0; k16 < 2; k16++) {
            uint4 ah[2], al[2];
#pragma unroll
            for (int tm = 0; tm < 2; tm++) {
                int m16 = wm * 2 + tm;
                const char* pA = base + (m16 * 2 + k16) * AREG_B + lane * 16;
                ah[tm] = *(const uint4*)pA;
                al[tm] = *(const uint4*)(pA + AMAT_B);
            }
#pragma unroll
            for (int tn = 0; tn < 4; tn++) {
                int n8 = wn * 4 + tn;
                const char* pB = base + 2 * AMAT_B + (n8 * 2 + k16) * BREG_B + lane * 8;
                uint2 bh = *(const uint2*)pB;
                uint2 bl = *(const uint2*)(pB + BMAT_B);
#pragma unroll
                for (int tm = 0; tm < 2; tm++) {
                    mma16(acc[tm][tn], ah[tm], bh);
                    mma16(acc[tm][tn], al[tm], bh);
                    mma16(acc[tm][tn], ah[tm], bl);
                }
            }
        }
    };

    const int NIT = K >> 5;
    do_ldg();
    do_sts(0);
    __syncthreads();
    for (int it = 0; it < NIT; it++) {
        if (it + 1 < NIT) do_ldg();
        do_comp(it & 1);
        if (it + 1 < NIT) do_sts((it + 1) & 1);
        __syncthreads();
    }

#pragma unroll
    for (int tm = 0; tm < 2; tm++) {
        int r0 = wm * 32 + tm * 16 + g;
        float s0 = rs_s[r0], s1 = rs_s[r0 + 8];
        size_t o0 = (size_t)ridx_s[r0] * HID;
        size_t o1 = (size_t)ridx_s[r0 + 8] * HID;
#pragma unroll
        for (int tn = 0; tn < 4; tn++) {
            int n0 = nb * 128 + wn * 32 + tn * 8 + 2 * tg;
            *(float2*)(C + o0 + n0) = make_float2(acc[tm][tn][0] * s0, acc[tm][tn][1] * s0);
            *(float2*)(C + o1 + n0) = make_float2(acc[tm][tn][2] * s1, acc[tm][tn][3] * s1);
        }
    }
}

// ---- coalesced transpose + fp16-split ---------------------------------------
__global__ void k_wsplitT(const float* __restrict__ W, __half* __restrict__ hi,
                          __half* __restrict__ lo, int K, int N) {
    __shared__ float tile[32][33];
    int kb = blockIdx.y * 32, nb = blockIdx.x * 32;
    int tx = threadIdx.x, ty = threadIdx.y;
#pragma unroll
    for (int r = ty; r < 32; r += 8)
        tile[r][tx] = W[(size_t)(kb + r) * N + nb + tx];
    __syncthreads();
#pragma unroll
    for (int r = ty; r < 32; r += 8) {
        float v = tile[tx][r];
        __half h = __float2half_rn(v);
        size_t o = (size_t)(nb + r) * K + kb + tx;
        hi[o] = h;
        lo[o] = __float2half_rn(v - __half2float(h));
    }
}

// ---- W2+W3 in one launch (blockIdx.z selects) -------------------------------
__global__ void k_wsplitT2(const float* __restrict__ Wa, __half* __restrict__ hia,
                           __half* __restrict__ loa, const float* __restrict__ Wb,
                           __half* __restrict__ hib, __half* __restrict__ lob) {
    __shared__ float tile[32][33];
    const float* W = blockIdx.z ? Wb : Wa;
    __half* hi = blockIdx.z ? hib : hia;
    __half* lo = blockIdx.z ? lob : loa;
    int kb = blockIdx.y * 32, nb = blockIdx.x * 32;
    int tx = threadIdx.x, ty = threadIdx.y;
#pragma unroll
    for (int r = ty; r < 32; r += 8)
        tile[r][tx] = W[(size_t)(kb + r) * HID + nb + tx];
    __syncthreads();
#pragma unroll
    for (int r = ty; r < 32; r += 8) {
        float v = tile[tx][r];
        __half h = __float2half_rn(v);
        size_t o = (size_t)(nb + r) * HID + kb + tx;
        hi[o] = h;
        lo[o] = __float2half_rn(v - __half2float(h));
    }
}

// ---------------- graph preprocessing ---------------------------------------
__global__ void k_init() {
    int i = blockIdx.x * blockDim.x + threadIdx.x;
    if (i < NN) { g_cnt[i] = 0; g_nmask[i] = 1.f; g_rows[i] = 1.f; g_iota[i] = i; }
}

__global__ void k_count(const int* __restrict__ dst) {
    int e = blockIdx.x * blockDim.x + threadIdx.x;
    if (e < EE) atomicAdd(&g_cnt[dst[e]], 1);
}

__global__ void k_scan() {   // CSR offsets + layer-1 dinv
    __shared__ int part[1024];
    int t = threadIdx.x;
    int base = t * 32;
    int s = 0;
#pragma unroll
    for (int i = 0; i < 32; i++) s += g_cnt[base + i];
    part[t] = s;
    __syncthreads();
    for (int off = 1; off < 1024; off <<= 1) {
        int v = (t >= off) ? part[t - off] : 0;
        __syncthreads();
        part[t] += v;
        __syncthreads();
    }
    int run = (t == 0) ? 0 : part[t - 1];
#pragma unroll
    for (int i = 0; i < 32; i++) {
        int c = g_cnt[base + i];
        g_off[base + i] = run;
        g_cur[base + i] = run;
        g_dinv[base + i] = rsqrtf((float)c + 1.f);
        run += c;
    }
    if (t == 1023) g_off[NN] = run;
}

__global__ void k_scatter(const int* __restrict__ src, const int* __restrict__ dst) {
    int e = blockIdx.x * blockDim.x + threadIdx.x;
    if (e < EE) {
        int p = atomicAdd(&g_cur[dst[e]], 1);
        g_csr[p] = src[e];
    }
}

// ---- agg + lrelu + fused pool dots; optional active-neighbor compaction ----
__global__ void k_agg(const float* __restrict__ bias, const float* __restrict__ wr,
                      const float* __restrict__ wo, int dopool, int allact,
                      const int* __restrict__ map) {
    __shared__ float s_ds[128];
    __shared__ int   s_src[128];
    __shared__ float s2[8];
    __shared__ int   s_cnt;
    int v = map[blockIdx.x];
    int c = threadIdx.x;
    int lane = c & 31;
    float dv = g_dinv[v];
    int e0 = g_off[v], deg = g_off[v + 1] - e0;

    float4 a = make_float4(0.f, 0.f, 0.f, 0.f);
    for (int base = 0; base < deg; base += 128) {
        int n = deg - base; if (n > 128) n = 128;
        int nact;
        if (allact) {
            if (c < n) {
                int s = g_csr[e0 + base + c];
                s_src[c] = s;
                s_ds[c] = g_dinv[s];
            }
            nact = n;
            __syncthreads();
        } else {
            if (c == 0) s_cnt = 0;
            __syncthreads();
            bool inb = c < n;
            int s = 0; float ds = 0.f;
            if (inb) { s = g_csr[e0 + base + c]; ds = g_dinv[s]; }
            bool act = inb && (ds != 0.f);
            unsigned m = __ballot_sync(0xffffffffu, act);
            int rank = __popc(m & ((1u << lane) - 1));
            int wbase = 0;
            if (lane == 0) wbase = atomicAdd(&s_cnt, __popc(m));
            wbase = __shfl_sync(0xffffffffu, wbase, 0);
            if (act) { s_src[wbase + rank] = s; s_ds[wbase + rank] = ds; }
            __syncthreads();
            nact = s_cnt;
        }
        int i = 0;
        for (; i + 2 <= nact; i += 2) {
            float ds0 = s_ds[i],   ds1 = s_ds[i + 1];
            float4 t0 = *((const float4*)(g_t + (size_t)s_src[i]     * HID) + c);
            float4 t1 = *((const float4*)(g_t + (size_t)s_src[i + 1] * HID) + c);
            a.x += ds0 * t0.x + ds1 * t1.x;
            a.y += ds0 * t0.y + ds1 * t1.y;
            a.z += ds0 * t0.z + ds1 * t1.z;
            a.w += ds0 * t0.w + ds1 * t1.w;
        }
        if (i < nact) {
            float ds0 = s_ds[i];
            float4 t0 = *((const float4*)(g_t + (size_t)s_src[i] * HID) + c);
            a.x += ds0 * t0.x; a.y += ds0 * t0.y;
            a.z += ds0 * t0.z; a.w += ds0 * t0.w;
        }
        __syncthreads();
    }

    float4 tv = *((const float4*)(g_t + (size_t)v * HID) + c);
    float4 bi = *((const float4*)bias + c);
    float dv2 = dv * dv;
    float4 h;
    h.x = lrelu(dv * a.x + dv2 * tv.x + bi.x);
    h.y = lrelu(dv * a.y + dv2 * tv.y + bi.y);
    h.z = lrelu(dv * a.z + dv2 * tv.z + bi.z);
    h.w = lrelu(dv * a.w + dv2 * tv.w + bi.w);
    *((float4*)(g_h + (size_t)v * HID) + c) = h;

    if (dopool) {
        float4 r4 = *((const float4*)wr + c);
        float4 o4 = *((const float4*)wo + c);
        float pr = h.x * r4.x + h.y * r4.y + h.z * r4.z + h.w * r4.w;
        float po = h.x * o4.x + h.y * o4.y + h.z * o4.z + h.w * o4.w;
#pragma unroll
        for (int o = 16; o > 0; o >>= 1) {
            pr += __shfl_down_sync(0xffffffff, pr, o);
            po += __shfl_down_sync(0xffffffff, po, o);
        }
        int wd = c >> 5;
        if (lane == 0) { s2[wd * 2] = pr; s2[wd * 2 + 1] = po; }
        __syncthreads();
        if (c == 0) {
            g_sr[v] = s2[0] + s2[2] + s2[4] + s2[6];
            g_so[v] = s2[1] + s2[3] + s2[5] + s2[7];
        }
    }
}

// ---- half-batch score (nodebase = half * HNODE) -----------------------------
__global__ void k_score(const float* __restrict__ br, int nodebase) {
    int v = nodebase + blockIdx.x * blockDim.x + threadIdx.x;
    if (g_nmask[v] <= 0.f) { g_score[v] = -1e30f; return; }
    float s = br[0] + g_so[v];
    int e0 = g_off[v], e1 = g_off[v + 1];
    for (int i = e0; i < e1; i++) s += g_sr[g_csr[i]];
    g_score[v] = s;
}

// ---- per-graph: radix topk + mask/rows/sr-zero + compact + fused next-deg --
__global__ void __launch_bounds__(1024)
k_topk(int goff, int kkeep, int* __restrict__ ridx) {
    __shared__ float    sc[NPG];
    __shared__ unsigned key[NPG];
    __shared__ int hist[256];
    __shared__ int sfx[256];
    __shared__ int wsum[32];
    __shared__ int s_bin, s_remk;
    __shared__ unsigned s_pref;
    int gph = goff + blockIdx.x, t = threadIdx.x;
    int base = gph * NPG;

    for (int i = t; i < NPG; i += 1024) {
        float s = g_score[base + i];
        sc[i] = s;
        unsigned u = __float_as_uint(s);
        key[i] = (u & 0x80000000u) ? ~u : (u | 0x80000000u);
    }
    if (t == 0) { s_remk = kkeep; s_pref = 0u; }
    __syncthreads();

    for (int shift = 24; shift >= 0; shift -= 8) {
        if (t < 256) hist[t] = 0;
        __syncthreads();
        unsigned pref = s_pref;
        int remk = s_remk;
        for (int i = t; i < NPG; i += 1024) {
            unsigned u = key[i];
            bool ok = (shift == 24) || ((u >> (shift + 8)) == pref);
            if (ok) atomicAdd(&hist[(u >> shift) & 255], 1);
        }
        __syncthreads();
        if (t < 256) sfx[t] = hist[t];
        __syncthreads();
        for (int off = 1; off < 256; off <<= 1) {
            int v2 = 0;
            if (t < 256 && t + off < 256) v2 = sfx[t + off];
            __syncthreads();
            if (t < 256) sfx[t] += v2;
            __syncthreads();
        }
        if (t < 256) {
            int excl = (t < 255) ? sfx[t + 1] : 0;
            if (excl < remk && remk <= excl + hist[t]) {
                s_bin = t;
                s_remk = remk - excl;
            }
        }
        __syncthreads();
        if (t == 0) s_pref = (s_pref << 8) | (unsigned)s_bin;
        __syncthreads();
    }
    unsigned Tkey = s_pref;

    // keep mask -> global nmask/rows (+zero sr of dropped); keep -> sc
    for (int i = t; i < NPG; i += 1024) {
        int v = base + i;
        float keep = (key[i] >= Tkey) ? 1.f : 0.f;
        g_nmask[v] = keep;
        g_rows[v] = keep * tanhf(sc[i]);
        if (keep == 0.f) g_sr[v] = 0.f;
        sc[i] = keep;
    }
    __syncthreads();

    // ordered compact (thread t owns elements [4t, 4t+4))
    int k4 = t * 4;
    int cnt = 0;
#pragma unroll
    for (int j = 0; j < 4; j++) cnt += (sc[k4 + j] > 0.f) ? 1 : 0;
    int lane_ = t & 31, w_ = t >> 5;
    int x = cnt;
#pragma unroll
    for (int o = 1; o < 32; o <<= 1) {
        int y = __shfl_up_sync(0xffffffff, x, o);
        if (lane_ >= o) x += y;
    }
    if (lane_ == 31) wsum[w_] = x;
    __syncthreads();
    if (w_ == 0) {
        int y = wsum[lane_];
#pragma unroll
        for (int o = 1; o < 32; o <<= 1) {
            int z = __shfl_up_sync(0xffffffff, y, o);
            if (lane_ >= o) y += z;
        }
        wsum[lane_] = y;
    }
    __syncthreads();
    int pos = x - cnt + (w_ ? wsum[w_ - 1] : 0);
#pragma unroll
    for (int j = 0; j < 4; j++) {
        if (sc[k4 + j] > 0.f) { ridx[gph * kkeep + pos] = base + k4 + j; pos++; }
    }

    // fused next-layer deg: neighbors are in-graph; keep is in sc (unchanged)
    for (int i = t; i < NPG; i += 1024) {
        int v = base + i;
        float dv = 0.f;
        if (sc[i] > 0.f) {
            float s = 1.f;
            int e0 = g_off[v], e1 = g_off[v + 1];
            for (int e = e0; e < e1; e++) s += sc[g_csr[e] - base];
            dv = rsqrtf(s);
        }
        g_dinv[v] = dv;
    }
}

// ---------------- readout (half batch; goff = first graph) -------------------
__global__ void k_pool1(int goff, const int* __restrict__ ridx3) {
    int g = goff + (blockIdx.x >> 4), ch = blockIdx.x & 15, c = threadIdx.x;
    const int* rp = ridx3 + g * K2 + ch * 64;
    float sum = 0.f, mx = -3.4e38f;
    for (int n = 0; n < 64; n++) {
        int node = rp[n];
        float h = g_h[(size_t)node * HID + c];
        sum += h;
        mx = fmaxf(mx, h);
    }
    g_pp_sum[(size_t)(g * 16 + ch) * HID + c] = sum;
    g_pp_max[(size_t)(g * 16 + ch) * HID + c] = mx;
}

__global__ void __launch_bounds__(512)
k_head(int goff, const float* __restrict__ fc1w, const float* __restrict__ fc1b,
       const float* __restrict__ fc2w, const float* __restrict__ fc2b,
       float* __restrict__ out) {
    __shared__ float gp[2 * HID];
    __shared__ float f1[HID];
    int g = goff + blockIdx.x, c = threadIdx.x;

    float sum = 0.f, mx = -3.4e38f;
    for (int j = 0; j < 16; j++) {
        sum += g_pp_sum[(size_t)(g * 16 + j) * HID + c];
        mx = fmaxf(mx, g_pp_max[(size_t)(g * 16 + j) * HID + c]);
    }
    gp[c] = sum / (float)K2;
    gp[HID + c] = mx;
    __syncthreads();

    float s = fc1b[c];
    for (int k = 0; k < 2 * HID; k++) s = fmaf(gp[k], fc1w[k * HID + c], s);
    f1[c] = lrelu(s);
    __syncthreads();

    if (c < NCLS) {
        float o = fc2b[c];
        for (int k = 0; k < HID; k++) o = fmaf(f1[k], fc2w[k * NCLS + c], o);
        out[g * NCLS + c] = o;
    }
}

// ---------------- launch -----------------------------------------------------
extern "C" void kernel_launch(void* const* d_in, const int* in_sizes, int n_in,
                              void* d_out, int out_size) {
    const float* x     = (const float*)d_in[0];
    const int*   esrc  = (const int*)d_in[1];
    const int*   edst  = (const int*)d_in[2];
    const float* W1    = (const float*)d_in[3];
    const float* b1    = (const float*)d_in[4];
    const float* p1wr  = (const float*)d_in[5];
    const float* p1br  = (const float*)d_in[6];
    const float* p1wo  = (const float*)d_in[7];
    const float* W2    = (const float*)d_in[8];
    const float* b2    = (const float*)d_in[9];
    const float* p2wr  = (const float*)d_in[10];
    const float* p2br  = (const float*)d_in[11];
    const float* p2wo  = (const float*)d_in[12];
    const float* W3    = (const float*)d_in[13];
    const float* b3    = (const float*)d_in[14];
    const float* fc1w  = (const float*)d_in[15];
    const float* fc1b  = (const float*)d_in[16];
    const float* fc2w  = (const float*)d_in[17];
    const float* fc2b  = (const float*)d_in[18];
    float* out = (float*)d_out;

    float*  dT;     cudaGetSymbolAddress((void**)&dT, g_t);
    float*  dH;     cudaGetSymbolAddress((void**)&dH, g_h);
    float*  dRS;    cudaGetSymbolAddress((void**)&dRS, g_rows);
    __half* dW1hi;  cudaGetSymbolAddress((void**)&dW1hi, g_w1t_hi);
    __half* dW1lo;  cudaGetSymbolAddress((void**)&dW1lo, g_w1t_lo);
    __half* dW2hi;  cudaGetSymbolAddress((void**)&dW2hi, g_w2t_hi);
    __half* dW2lo;  cudaGetSymbolAddress((void**)&dW2lo, g_w2t_lo);
    __half* dW3hi;  cudaGetSymbolAddress((void**)&dW3hi, g_w3t_hi);
    __half* dW3lo;  cudaGetSymbolAddress((void**)&dW3lo, g_w3t_lo);
    int*    dIota;  cudaGetSymbolAddress((void**)&dIota, g_iota);
    int*    dR2;    cudaGetSymbolAddress((void**)&dR2, g_ridx2);
    int*    dR3;    cudaGetSymbolAddress((void**)&dR3, g_ridx3);

    static cudaStream_t s_side = 0;
    static cudaEvent_t  e_fork = 0, e_w1 = 0, e_csr = 0, e_w23 = 0, e_join = 0;
    static int cfg_done = 0;
    if (!cfg_done) {   // first (non-captured) call only; host-side config
        cudaFuncSetAttribute(mma_gemm, cudaFuncAttributeMaxDynamicSharedMemorySize, SM_BYTES);
        cudaStreamCreateWithFlags(&s_side, cudaStreamNonBlocking);
        cudaEventCreateWithFlags(&e_fork, cudaEventDisableTiming);
        cudaEventCreateWithFlags(&e_w1,   cudaEventDisableTiming);
        cudaEventCreateWithFlags(&e_csr,  cudaEventDisableTiming);
        cudaEventCreateWithFlags(&e_w23,  cudaEventDisableTiming);
        cudaEventCreateWithFlags(&e_join, cudaEventDisableTiming);
        cfg_done = 1;
    }

    // half-batch chain (after this half's GEMM1; CSR + W2/W3 must be ready)
    auto chain = [&](cudaStream_t sg, int half) {
        int goff = half * HGRAPH;
        int nb = half * HNODE;
        k_agg<<<HNODE, 128, 0, sg>>>(b1, p1wr, p1wo, 1, 1, dIota + nb);
        k_score<<<HNODE / 256, 256, 0, sg>>>(p1br, nb);
        k_topk<<<HGRAPH, 1024, 0, sg>>>(goff, K1, dR2);
        mma_gemm<<<dim3(HID / 128, (HGRAPH * K1) / 128), 512, SM_BYTES, sg>>>(
            dH, dW2hi, dW2lo, dRS, dR2 + goff * K1, dT, HID);
        k_agg<<<HGRAPH * K1, 128, 0, sg>>>(b2, p2wr, p2wo, 1, 0, dR2 + goff * K1);
        k_score<<<HNODE / 256, 256, 0, sg>>>(p2br, nb);
        k_topk<<<HGRAPH, 1024, 0, sg>>>(goff, K2, dR3);
        mma_gemm<<<dim3(HID / 128, (HGRAPH * K2) / 128), 512, SM_BYTES, sg>>>(
            dH, dW3hi, dW3lo, dRS, dR3 + goff * K2, dT, HID);
        k_agg<<<HGRAPH * K2, 128, 0, sg>>>(b3, (const float*)0, (const float*)0, 0, 0,
                                           dR3 + goff * K2);
        k_pool1<<<HGRAPH * 16, HID, 0, sg>>>(goff, dR3);
        k_head<<<HGRAPH, HID, 0, sg>>>(goff, fc1w, fc1b, fc2w, fc2b, out);
    };

    // ---- shared preprocessing ----
    k_init<<<NN / 256, 256>>>();
    cudaEventRecord(e_fork, 0);
    cudaStreamWaitEvent(s_side, e_fork, 0);

    // side: CSR build, then W2/W3 splits
    k_count<<<EE / 256, 256, 0, s_side>>>(edst);
    k_scan<<<1, 1024, 0, s_side>>>();
    k_scatter<<<EE / 256, 256, 0, s_side>>>(esrc, edst);
    cudaEventRecord(e_csr, s_side);
    k_wsplitT2<<<dim3(HID / 32, HID / 32, 2), dim3(32, 8), 0, s_side>>>(
        W2, dW2hi, dW2lo, W3, dW3hi, dW3lo);
    cudaEventRecord(e_w23, s_side);

    // main: W1 split
    k_wsplitT<<<dim3(HID / 32, INC / 32), dim3(32, 8)>>>(W1, dW1hi, dW1lo, INC, HID);
    cudaEventRecord(e_w1, 0);

    // ---- half A on main: GEMM1 rows 0..HNODE-1, then chain for graphs 0-3 ----
    mma_gemm<<<dim3(HID / 128, HNODE / 128), 512, SM_BYTES>>>(
        x, dW1hi, dW1lo, dRS, dIota, dT, INC);
    cudaStreamWaitEvent(0, e_csr, 0);
    cudaStreamWaitEvent(0, e_w23, 0);
    chain(0, 0);

    // ---- half B on side: GEMM1 rows HNODE.., then chain for graphs 4-7 ----
    cudaStreamWaitEvent(s_side, e_w1, 0);
    mma_gemm<<<dim3(HID / 128, HNODE / 128), 512, SM_BYTES, s_side>>>(
        x, dW1hi, dW1lo, dRS, dIota + HNODE, dT, INC);
    chain(s_side, 1);
    cudaEventRecord(e_join, s_side);

    // join
    cudaStreamWaitEvent(0, e_join, 0);
}